// round 6
// baseline (speedup 1.0000x reference)
#include <cuda_runtime.h>
#include <cuda_bf16.h>
#include <math.h>
#include <stdint.h>

// ---------------------------------------------------------------- constants
#define S_LEN 2048
#define H_DIM 2048
#define NHEAD 16
#define DQK   128
#define DV    64
#define KVR   256
#define NEXP  8
#define INTER 1408
#define NFC1  (NEXP*INTER)   // 11264
#define CKV_P 512            // padded kv_a output width

#define KB_H    (H_DIM/64)      // 32
#define KB_KVR  (KVR/64)        // 4
#define KB_CTX  ((NHEAD*DV)/64) // 16
#define KB_FC2  (NFC1/64)       // 176

// ---------------------------------------------------------------- scratch (fp32)
__device__ float g_sa  [S_LEN*H_DIM];
__device__ float g_q   [S_LEN*H_DIM];
__device__ float g_ckv [S_LEN*CKV_P];
__device__ float g_kvn [S_LEN*KVR];
__device__ float g_kv  [S_LEN*H_DIM];
__device__ float g_kpe [S_LEN*64];
__device__ float g_x2  [S_LEN*H_DIM];
__device__ float g_mlp [S_LEN*H_DIM];
__device__ float g_pr  [S_LEN*NEXP];

// ---------------------------------------------------------------- scratch (blocked bf16 hi/lo)
__device__ __nv_bfloat16 g_sa_h [S_LEN*H_DIM],   g_sa_l [S_LEN*H_DIM];
__device__ __nv_bfloat16 g_kvn_h[S_LEN*KVR],     g_kvn_l[S_LEN*KVR];
__device__ __nv_bfloat16 g_mlp_h[S_LEN*H_DIM],   g_mlp_l[S_LEN*H_DIM];
__device__ __nv_bfloat16 g_ctx_h[S_LEN*NHEAD*DV],g_ctx_l[S_LEN*NHEAD*DV];
__device__ __nv_bfloat16 g_hb_h [(size_t)S_LEN*NFC1], g_hb_l [(size_t)S_LEN*NFC1];
__device__ __nv_bfloat16 g_qw_h [H_DIM*H_DIM],   g_qw_l [H_DIM*H_DIM];
__device__ __nv_bfloat16 g_kva_h[CKV_P*H_DIM],   g_kva_l[CKV_P*H_DIM];
__device__ __nv_bfloat16 g_kbw_h[H_DIM*KVR],     g_kbw_l[H_DIM*KVR];
__device__ __nv_bfloat16 g_ow_h [H_DIM*NHEAD*DV],g_ow_l [H_DIM*NHEAD*DV];
__device__ __nv_bfloat16 g_f1_h [(size_t)NFC1*H_DIM], g_f1_l [(size_t)NFC1*H_DIM];
__device__ __nv_bfloat16 g_f2_h [(size_t)H_DIM*NFC1], g_f2_l [(size_t)H_DIM*NFC1];
__device__ __nv_bfloat16 g_qb_h[S_LEN*H_DIM],    g_qb_l[S_LEN*H_DIM];
__device__ __nv_bfloat16 g_kb_h[S_LEN*H_DIM],    g_kb_l[S_LEN*H_DIM];
__device__ __nv_bfloat16 g_vt_h[S_LEN*NHEAD*DV], g_vt_l[S_LEN*NHEAD*DV];

// ---------------------------------------------------------------- helpers
__device__ __forceinline__ uint32_t smem_u32(const void* p) {
    uint32_t a;
    asm("{ .reg .u64 t; cvta.to.shared.u64 t, %1; cvt.u32.u64 %0, t; }" : "=r"(a) : "l"(p));
    return a;
}
#define SWZ(off) ((off) ^ (((off) >> 3) & 0x70u))

__device__ __forceinline__ void ldsm_x4(uint32_t* r, uint32_t addr) {
    asm volatile("ldmatrix.sync.aligned.m8n8.x4.shared.b16 {%0,%1,%2,%3}, [%4];"
                 : "=r"(r[0]), "=r"(r[1]), "=r"(r[2]), "=r"(r[3]) : "r"(addr));
}
__device__ __forceinline__ void mma_bf16(float* c, const uint32_t* a, const uint32_t* b) {
    asm volatile("mma.sync.aligned.m16n8k16.row.col.f32.bf16.bf16.f32 "
                 "{%0,%1,%2,%3}, {%4,%5,%6,%7}, {%8,%9}, {%0,%1,%2,%3};"
                 : "+f"(c[0]), "+f"(c[1]), "+f"(c[2]), "+f"(c[3])
                 : "r"(a[0]), "r"(a[1]), "r"(a[2]), "r"(a[3]), "r"(b[0]), "r"(b[1]));
}
#define MBAR_INIT(a, c) asm volatile("mbarrier.init.shared.b64 [%0], %1;" :: "r"(a), "r"(c) : "memory")
#define MBAR_EXPECT(a, b) asm volatile("mbarrier.arrive.expect_tx.shared.b64 _, [%0], %1;" :: "r"(a), "r"(b) : "memory")
#define MBAR_WAIT(a, ph) do { \
    asm volatile("{\n\t.reg .pred P1;\n\tWL_%=:\n\t" \
        "mbarrier.try_wait.parity.acquire.cta.shared::cta.b64 P1, [%0], %1, 0x989680;\n\t" \
        "@P1 bra.uni WD_%=;\n\tbra.uni WL_%=;\n\tWD_%=:\n\t}" \
        :: "r"(a), "r"(ph) : "memory"); } while (0)
__device__ __forceinline__ void bulk_g2s(uint32_t dst, const void* src, uint32_t bytes, uint32_t mbar) {
    asm volatile("cp.async.bulk.shared::cluster.global.mbarrier::complete_tx::bytes [%0], [%1], %2, [%3];"
                 :: "r"(dst), "l"(src), "r"(bytes), "r"(mbar) : "memory");
}

__device__ __forceinline__ uint32_t pack_hilo(float x, float y, uint32_t& lo) {
    __nv_bfloat16 hx = __float2bfloat16(x), hy = __float2bfloat16(y);
    __nv_bfloat16 lx = __float2bfloat16(x - __bfloat162float(hx));
    __nv_bfloat16 ly = __float2bfloat16(y - __bfloat162float(hy));
    lo = (uint32_t)__bfloat16_as_ushort(lx) | ((uint32_t)__bfloat16_as_ushort(ly) << 16);
    return (uint32_t)__bfloat16_as_ushort(hx) | ((uint32_t)__bfloat16_as_ushort(hy) << 16);
}
__device__ __forceinline__ void split8(const float* v, uint4& ph, uint4& pl) {
    uint32_t hh[8], ll[8];
    #pragma unroll
    for (int j = 0; j < 8; j++) {
        __nv_bfloat16 h = __float2bfloat16(v[j]);
        __nv_bfloat16 l = __float2bfloat16(v[j] - __bfloat162float(h));
        hh[j] = (uint32_t)__bfloat16_as_ushort(h);
        ll[j] = (uint32_t)__bfloat16_as_ushort(l);
    }
    ph = make_uint4(hh[0]|(hh[1]<<16), hh[2]|(hh[3]<<16), hh[4]|(hh[5]<<16), hh[6]|(hh[7]<<16));
    pl = make_uint4(ll[0]|(ll[1]<<16), ll[2]|(ll[3]<<16), ll[4]|(ll[5]<<16), ll[6]|(ll[7]<<16));
}
__device__ __forceinline__ size_t blk_chunk_off(int blk_idx, int row, int c8) {
    uint32_t inner = (uint32_t)row * 128u + (uint32_t)c8 * 16u;
    return ((size_t)blk_idx << 14) + SWZ(inner);
}

// ---------------------------------------------------------------- weight converts
__global__ void cvt_blk_kernel(const float* __restrict__ src,
                               __nv_bfloat16* __restrict__ H, __nv_bfloat16* __restrict__ L,
                               int Npad, int Nreal, int K) {
    const int KC = K >> 3;
    const int KBk = K >> 6;
    const size_t tot = (size_t)Npad * KC;
    for (size_t idx = (size_t)blockIdx.x * blockDim.x + threadIdx.x; idx < tot;
         idx += (size_t)gridDim.x * blockDim.x) {
        int n = (int)(idx / KC), c = (int)(idx - (size_t)n * KC);
        float v[8];
        if (n < Nreal) {
            const float4 f0 = *(const float4*)(src + (size_t)n * K + c * 8);
            const float4 f1 = *(const float4*)(src + (size_t)n * K + c * 8 + 4);
            v[0]=f0.x; v[1]=f0.y; v[2]=f0.z; v[3]=f0.w; v[4]=f1.x; v[5]=f1.y; v[6]=f1.z; v[7]=f1.w;
        } else {
            #pragma unroll
            for (int j = 0; j < 8; j++) v[j] = 0.f;
        }
        uint4 ph, pl; split8(v, ph, pl);
        size_t off = blk_chunk_off((n >> 7) * KBk + (c >> 3), n & 127, c & 7);
        *(uint4*)((char*)H + off) = ph;
        *(uint4*)((char*)L + off) = pl;
    }
}

__global__ void cvt_fc2_blk_kernel(const float* __restrict__ w,
                                   __nv_bfloat16* __restrict__ H, __nv_bfloat16* __restrict__ L) {
    const int KC = NFC1 >> 3;
    const size_t tot = (size_t)H_DIM * KC;
    for (size_t idx = (size_t)blockIdx.x * blockDim.x + threadIdx.x; idx < tot;
         idx += (size_t)gridDim.x * blockDim.x) {
        int n = (int)(idx / KC), c = (int)(idx - (size_t)n * KC);
        int k0 = c * 8;
        int e = k0 / INTER, i = k0 - e * INTER;
        const float* sp = w + ((size_t)e * H_DIM + n) * INTER + i;
        float v[8];
        const float4 f0 = *(const float4*)sp;
        const float4 f1 = *(const float4*)(sp + 4);
        v[0]=f0.x; v[1]=f0.y; v[2]=f0.z; v[3]=f0.w; v[4]=f1.x; v[5]=f1.y; v[6]=f1.z; v[7]=f1.w;
        uint4 ph, pl; split8(v, ph, pl);
        size_t off = blk_chunk_off((n >> 7) * KB_FC2 + (c >> 3), n & 127, c & 7);
        *(uint4*)((char*)H + off) = ph;
        *(uint4*)((char*)L + off) = pl;
    }
}

// ---------------------------------------------------------------- rmsnorm (+blocked hi/lo)
__global__ void rmsnorm_kernel(const float* __restrict__ x, const float* __restrict__ w,
                               float* __restrict__ y,
                               __nv_bfloat16* __restrict__ yh, __nv_bfloat16* __restrict__ yl,
                               int W, int xs, int KBk)
{
    int s = blockIdx.x, tid = threadIdx.x;
    const float* xr = x + (size_t)s * xs;
    float ss = 0.f;
    for (int i = tid; i < W; i += 256) { float v = xr[i]; ss += v * v; }
    __shared__ float red[256];
    red[tid] = ss; __syncthreads();
    for (int o = 128; o > 0; o >>= 1) { if (tid < o) red[tid] += red[tid + o]; __syncthreads(); }
    float inv = rsqrtf(red[0] / (float)W + 1e-6f);
    float* yr = y + (size_t)s * W;
    const int KC = W >> 3;
    for (int c = tid; c < KC; c += 256) {
        float v[8];
        #pragma unroll
        for (int j = 0; j < 8; j++) {
            int i = c * 8 + j;
            v[j] = w[i] * xr[i] * inv;
            yr[i] = v[j];
        }
        uint4 ph, pl; split8(v, ph, pl);
        size_t off = blk_chunk_off((s >> 7) * KBk + (c >> 3), s & 127, c & 7);
        *(uint4*)((char*)yh + off) = ph;
        *(uint4*)((char*)yl + off) = pl;
    }
}

// ---------------------------------------------------------------- rope
__global__ void rope_kernel(const int* __restrict__ positions,
                            float* __restrict__ q,
                            const float* __restrict__ ckv,
                            float* __restrict__ kpe)
{
    int s = blockIdx.x;
    float p = (float)positions[s];
    for (int idx = threadIdx.x; idx < NHEAD * 32 + 32; idx += blockDim.x) {
        int j = idx & 31;
        float ang = p * powf(10000.0f, -(float)j * (1.0f / 32.0f));
        float c = cosf(ang), sn = sinf(ang);
        if (idx < NHEAD * 32) {
            int hh = idx >> 5;
            float* xp = q + (size_t)s * H_DIM + hh * DQK + 64;
            float x0 = xp[j], x1 = xp[j + 32];
            xp[j]      = x0 * c - x1 * sn;
            xp[j + 32] = x1 * c + x0 * sn;
        } else {
            const float* xp = ckv + (size_t)s * CKV_P + 256;
            float x0 = xp[j], x1 = xp[j + 32];
            kpe[(size_t)s * 64 + j]      = x0 * c - x1 * sn;
            kpe[(size_t)s * 64 + j + 32] = x1 * c + x0 * sn;
        }
    }
}

// ---------------------------------------------------------------- gate softmax
__global__ void gate_kernel(const float* __restrict__ x, const float* __restrict__ w,
                            float* __restrict__ probs)
{
    int s = blockIdx.x;
    int warp = threadIdx.x >> 5, lane = threadIdx.x & 31;
    const float* xr = x + (size_t)s * H_DIM;
    const float* wr = w + (size_t)warp * H_DIM;
    float acc = 0.f;
    for (int i = lane; i < H_DIM; i += 32) acc += xr[i] * wr[i];
    #pragma unroll
    for (int o = 16; o; o >>= 1) acc += __shfl_xor_sync(0xffffffffu, acc, o);
    __shared__ float lg[8];
    if (lane == 0) lg[warp] = acc;
    __syncthreads();
    if (threadIdx.x == 0) {
        float mx = lg[0];
        #pragma unroll
        for (int e = 1; e < 8; e++) mx = fmaxf(mx, lg[e]);
        float sum = 0.f, ev[8];
        #pragma unroll
        for (int e = 0; e < 8; e++) { ev[e] = __expf(lg[e] - mx); sum += ev[e]; }
        float invs = 1.f / sum;
        #pragma unroll
        for (int e = 0; e < 8; e++) probs[(size_t)s * 8 + e] = ev[e] * invs;
    }
}

// ---------------------------------------------------------------- attention input converts
__global__ void qk_cvt_kernel(const float* __restrict__ q, const float* __restrict__ kv,
                              const float* __restrict__ kpe,
                              __nv_bfloat16* __restrict__ QH, __nv_bfloat16* __restrict__ QL,
                              __nv_bfloat16* __restrict__ KH, __nv_bfloat16* __restrict__ KL)
{
    const int s = blockIdx.x, tid = threadIdx.x;
    const int h = tid >> 4, d = (tid & 15) * 8;
    const size_t off = ((size_t)((h * 16 + (s >> 7)) * 2 + (d >> 6)) << 14)
                       + SWZ((uint32_t)(s & 127) * 128u + (uint32_t)(d & 63) * 2u);
    {
        float v[8];
        #pragma unroll
        for (int j = 0; j < 8; j++) v[j] = q[(size_t)s * H_DIM + h * DQK + d + j];
        uint4 ph, pl; split8(v, ph, pl);
        *(uint4*)((char*)QH + off) = ph;
        *(uint4*)((char*)QL + off) = pl;
    }
    {
        float v[8];
        #pragma unroll
        for (int j = 0; j < 8; j++) {
            int dd = d + j;
            v[j] = (dd < 64) ? kv[(size_t)s * H_DIM + h * DQK + dd]
                             : kpe[(size_t)s * 64 + dd - 64];
        }
        uint4 ph, pl; split8(v, ph, pl);
        *(uint4*)((char*)KH + off) = ph;
        *(uint4*)((char*)KL + off) = pl;
    }
}

__global__ void vt_cvt_kernel(const float* __restrict__ kv,
                              __nv_bfloat16* __restrict__ VH, __nv_bfloat16* __restrict__ VL)
{
    __shared__ float vt[128][65];
    const int sb = blockIdx.x, h = blockIdx.y, tid = threadIdx.x;
    #pragma unroll
    for (int i = 0; i < 32; i++) {
        int idx = tid + i * 256;
        int r = idx >> 6, c = idx & 63;
        vt[r][c] = kv[(size_t)(sb * 128 + r) * H_DIM + h * DQK + 64 + c];
    }
    __syncthreads();
    #pragma unroll
    for (int i = 0; i < 4; i++) {
        int idx = tid + i * 256;
        int d = idx >> 4, s0 = (idx & 15) * 8;
        float v[8];
        #pragma unroll
        for (int j = 0; j < 8; j++) v[j] = vt[s0 + j][d];
        uint4 ph, pl; split8(v, ph, pl);
        size_t off = ((size_t)(h * 16 + sb) << 14) + (size_t)(s0 >> 6) * 8192u
                     + SWZ((uint32_t)d * 128u + (uint32_t)(s0 & 63) * 2u);
        *(uint4*)((char*)VH + off) = ph;
        *(uint4*)((char*)VL + off) = pl;
    }
}

// ---------------------------------------------------------------- bulk-copy split-bf16 GEMM
#define BG_STAGE_B  98304u
#define BG_SMEM     (1024 + 2 * 98304)
#define OFF_AH 0u
#define OFF_AL 16384u
#define OFF_BH 32768u
#define OFF_BL 65536u

template<int EPI>
__global__ __launch_bounds__(256, 1) void bgemm(
    const __nv_bfloat16* __restrict__ Abh, const __nv_bfloat16* __restrict__ Abl,
    const __nv_bfloat16* __restrict__ Bbh, const __nv_bfloat16* __restrict__ Bbl,
    int N, int KBk,
    float* __restrict__ C, const float* __restrict__ extra,
    __nv_bfloat16* __restrict__ Ch, __nv_bfloat16* __restrict__ Cl, int CKB)
{
    extern __shared__ char smem[];
    const uint32_t sb = smem_u32(smem);
    const uint32_t tb = (sb + 1023u) & ~1023u;
    const int tid = threadIdx.x, wid = tid >> 5, lane = tid & 31;
    const int n0 = blockIdx.x * 256, m0 = blockIdx.y * 128;
    const int mb = blockIdx.y, nb0 = blockIdx.x * 2;
    const int wm = (wid >> 2) * 64;
    const int wn = (wid & 3) * 64;
    const uint32_t bsel = (uint32_t)(wn >> 7) * 16384u;
    const int brow0 = wn & 64;

    if (tid == 0) { MBAR_INIT(sb, 1); MBAR_INIT(sb + 8, 1); }
    __syncthreads();

    auto load_stage = [&](int t) {
        const int s = t & 1;
        const uint32_t mb_addr = sb + s * 8;
        const uint32_t st = tb + s * BG_STAGE_B;
        MBAR_EXPECT(mb_addr, BG_STAGE_B);
        bulk_g2s(st + OFF_AH,          (const char*)Abh + (((size_t)mb * KBk + t) << 14), 16384u, mb_addr);
        bulk_g2s(st + OFF_AL,          (const char*)Abl + (((size_t)mb * KBk + t) << 14), 16384u, mb_addr);
        bulk_g2s(st + OFF_BH,          (const char*)Bbh + (((size_t)nb0 * KBk + t) << 14), 16384u, mb_addr);
        bulk_g2s(st + OFF_BH + 16384u, (const char*)Bbh + (((size_t)(nb0 + 1) * KBk + t) << 14), 16384u, mb_addr);
        bulk_g2s(st + OFF_BL,          (const char*)Bbl + (((size_t)nb0 * KBk + t) << 14), 16384u, mb_addr);
        bulk_g2s(st + OFF_BL + 16384u, (const char*)Bbl + (((size_t)(nb0 + 1) * KBk + t) << 14), 16384u, mb_addr);
    };

    if (tid == 0) { load_stage(0); if (KBk > 1) load_stage(1); }

    float acc[4][8][4];
    #pragma unroll
    for (int i = 0; i < 4; i++)
        #pragma unroll
        for (int j = 0; j < 8; j++)
            #pragma unroll
            for (int k = 0; k < 4; k++) acc[i][j][k] = 0.f;

    const uint32_t a_row = lane & 15, a_chk = lane >> 4;
    const uint32_t b_row = ((lane >> 4) & 1) * 8 + (lane & 7);
    const uint32_t b_chk = (lane >> 3) & 1;

    for (int t = 0; t < KBk; t++) {
        MBAR_WAIT(sb + (t & 1) * 8, (t >> 1) & 1);
        const uint32_t st = tb + (t & 1) * BG_STAGE_B;

        #pragma unroll
        for (int ks = 0; ks < 4; ks++) {
            uint32_t a_h[4][4], a_l[4][4], b_h[8][2], b_l[8][2];
            #pragma unroll
            for (int mt = 0; mt < 4; mt++) {
                uint32_t off = SWZ((uint32_t)(wm + mt * 16 + a_row) * 128u + (ks * 2 + a_chk) * 16u);
                ldsm_x4(a_h[mt], st + OFF_AH + off);
                ldsm_x4(a_l[mt], st + OFF_AL + off);
            }
            #pragma unroll
            for (int p = 0; p < 4; p++) {
                uint32_t off = SWZ((uint32_t)(brow0 + p * 16 + b_row) * 128u + (ks * 2 + b_chk) * 16u);
                uint32_t rh[4], rl[4];
                ldsm_x4(rh, st + OFF_BH + bsel + off);
                ldsm_x4(rl, st + OFF_BL + bsel + off);
                b_h[2*p][0]=rh[0]; b_h[2*p][1]=rh[1]; b_h[2*p+1][0]=rh[2]; b_h[2*p+1][1]=rh[3];
                b_l[2*p][0]=rl[0]; b_l[2*p][1]=rl[1]; b_l[2*p+1][0]=rl[2]; b_l[2*p+1][1]=rl[3];
            }
            // term-major passes: same-acc dependency distance = 32 MMAs
            #pragma unroll
            for (int mt = 0; mt < 4; mt++)
                #pragma unroll
                for (int nt = 0; nt < 8; nt++)
                    mma_bf16(acc[mt][nt], a_h[mt], b_h[nt]);
            #pragma unroll
            for (int mt = 0; mt < 4; mt++)
                #pragma unroll
                for (int nt = 0; nt < 8; nt++)
                    mma_bf16(acc[mt][nt], a_h[mt], b_l[nt]);
            #pragma unroll
            for (int mt = 0; mt < 4; mt++)
                #pragma unroll
                for (int nt = 0; nt < 8; nt++)
                    mma_bf16(acc[mt][nt], a_l[mt], b_h[nt]);
        }
        __syncthreads();
        if (tid == 0 && t + 2 < KBk) load_stage(t + 2);
    }

    #pragma unroll
    for (int mt = 0; mt < 4; mt++) {
        #pragma unroll
        for (int half = 0; half < 2; half++) {
            const int row = m0 + wm + mt * 16 + half * 8 + (lane >> 2);
            #pragma unroll
            for (int nt = 0; nt < 8; nt++) {
                const int col = n0 + wn + nt * 8 + (lane & 3) * 2;
                float v0 = acc[mt][nt][half * 2 + 0];
                float v1 = acc[mt][nt][half * 2 + 1];
                if (EPI == 0) {
                    *(float2*)&C[(size_t)row * N + col] = make_float2(v0, v1);
                } else if (EPI == 2) {
                    const float2 e2 = *(const float2*)&extra[(size_t)row * N + col];
                    *(float2*)&C[(size_t)row * N + col] = make_float2(v0 + e2.x, v1 + e2.y);
                } else {
                    float pf = extra[(size_t)row * NEXP + (col / INTER)];
                    float s0 = v0 / (1.f + __expf(-v0)) * pf;
                    float s1 = v1 / (1.f + __expf(-v1)) * pf;
                    uint32_t pl;
                    uint32_t ph = pack_hilo(s0, s1, pl);
                    uint32_t inner = (uint32_t)(row & 127) * 128u + (uint32_t)(col & 63) * 2u;
                    size_t off = (((size_t)(row >> 7) * CKB + (col >> 6)) << 14) + SWZ(inner);
                    *(uint32_t*)((char*)Ch + off) = ph;
                    *(uint32_t*)((char*)Cl + off) = pl;
                }
            }
        }
    }
}

// ---------------------------------------------------------------- tensor-core flash attention
#define AT_SMEM (1024 + 192 * 1024)

__global__ __launch_bounds__(256, 1) void attn_tc(
    const __nv_bfloat16* __restrict__ QHg, const __nv_bfloat16* __restrict__ QLg,
    const __nv_bfloat16* __restrict__ KHg, const __nv_bfloat16* __restrict__ KLg,
    const __nv_bfloat16* __restrict__ VHg, const __nv_bfloat16* __restrict__ VLg,
    __nv_bfloat16* __restrict__ Ch, __nv_bfloat16* __restrict__ Cl)
{
    extern __shared__ char smem[];
    const uint32_t sbb = smem_u32(smem);
    const uint32_t tb = (sbb + 1023u) & ~1023u;
    const uint32_t QH = tb, QL = tb + 32768u, KH = tb + 65536u, KL = tb + 98304u;
    const uint32_t VH0 = tb + 131072u, VL0 = tb + 163840u;

    const int tid = threadIdx.x, wid = tid >> 5, lane = tid & 31;
    const int idx = (int)gridDim.x - 1 - (int)blockIdx.x;
    const int qt = idx >> 4, h = idx & 15;
    const int wq = wid * 16;
    const int r = lane >> 2, c2 = (lane & 3) * 2;

    if (tid == 0) {
        MBAR_INIT(sbb, 1); MBAR_INIT(sbb + 8, 1);
    }
    __syncthreads();
    if (tid == 0) {
        MBAR_EXPECT(sbb, 65536u);
        bulk_g2s(QH, (const char*)QHg + ((size_t)(h * 16 + qt) << 15), 32768u, sbb);
        bulk_g2s(QL, (const char*)QLg + ((size_t)(h * 16 + qt) << 15), 32768u, sbb);
        MBAR_EXPECT(sbb + 8, 98304u);
        bulk_g2s(KH,  (const char*)KHg + ((size_t)(h * 16 + 0) << 15), 32768u, sbb + 8);
        bulk_g2s(KL,  (const char*)KLg + ((size_t)(h * 16 + 0) << 15), 32768u, sbb + 8);
        bulk_g2s(VH0, (const char*)VHg + ((size_t)(h * 16 + 0) << 14), 16384u, sbb + 8);
        bulk_g2s(VL0, (const char*)VLg + ((size_t)(h * 16 + 0) << 14), 16384u, sbb + 8);
    }

    float sc[16][4];
    float o[8][4];
    #pragma unroll
    for (int i = 0; i < 8; i++)
        #pragma unroll
        for (int j = 0; j < 4; j++) o[i][j] = 0.f;
    float m0 = -1e30f, m1 = -1e30f, l0 = 0.f, l1 = 0.f;
    const float SCL = 0.08838834764831845f * 1.44269504088896f;

    const uint32_t a_row = lane & 15, a_chk = lane >> 4;
    const uint32_t b_row = ((lane >> 4) & 1) * 8 + (lane & 7);
    const uint32_t b_chk = (lane >> 3) & 1;

    for (int kt = 0; kt <= qt; kt++) {
        MBAR_WAIT(sbb + 8, kt & 1);
        if (kt == 0) MBAR_WAIT(sbb, 0);

        // ---- S = Q K^T (3-term, term-major in groups of 4 p)
        #pragma unroll
        for (int nt = 0; nt < 16; nt++)
            #pragma unroll
            for (int j = 0; j < 4; j++) sc[nt][j] = 0.f;

        #pragma unroll
        for (int kc = 0; kc < 8; kc++) {
            const uint32_t db = (kc >> 2) * 16384u;
            const uint32_t acol = ((uint32_t)(kc * 16) + a_chk * 8u) & 63u;
            uint32_t aoff = db + SWZ((uint32_t)(wq + a_row) * 128u + acol * 2u);
            uint32_t a_h[4], a_l[4];
            ldsm_x4(a_h, QH + aoff);
            ldsm_x4(a_l, QL + aoff);
            const uint32_t bcol = ((uint32_t)(kc * 16) + b_chk * 8u) & 63u;
            #pragma unroll
            for (int pg = 0; pg < 2; pg++) {
                uint32_t bh[8][2], bl[8][2];
                #pragma unroll
                for (int p = 0; p < 4; p++) {
                    uint32_t boff = db + SWZ((uint32_t)((pg * 4 + p) * 16 + b_row) * 128u + bcol * 2u);
                    uint32_t rh[4], rl[4];
                    ldsm_x4(rh, KH + boff);
                    ldsm_x4(rl, KL + boff);
                    bh[2*p][0]=rh[0]; bh[2*p][1]=rh[1]; bh[2*p+1][0]=rh[2]; bh[2*p+1][1]=rh[3];
                    bl[2*p][0]=rl[0]; bl[2*p][1]=rl[1]; bl[2*p+1][0]=rl[2]; bl[2*p+1][1]=rl[3];
                }
                float (*scg)[4] = &sc[pg * 8];
                #pragma unroll
                for (int i = 0; i < 8; i++) mma_bf16(scg[i], a_h, bh[i]);
                #pragma unroll
                for (int i = 0; i < 8; i++) mma_bf16(scg[i], a_h, bl[i]);
                #pragma unroll
                for (int i = 0; i < 8; i++) mma_bf16(scg[i], a_l, bh[i]);
            }
        }
        __syncthreads();
        if (tid == 0 && kt < qt) {
            const int nt1 = kt + 1;
            const uint32_t vb = ((uint32_t)(nt1 & 1)) * 16384u;
            MBAR_EXPECT(sbb + 8, 98304u);
            bulk_g2s(KH,       (const char*)KHg + ((size_t)(h * 16 + nt1) << 15), 32768u, sbb + 8);
            bulk_g2s(KL,       (const char*)KLg + ((size_t)(h * 16 + nt1) << 15), 32768u, sbb + 8);
            bulk_g2s(VH0 + vb, (const char*)VHg + ((size_t)(h * 16 + nt1) << 14), 16384u, sbb + 8);
            bulk_g2s(VL0 + vb, (const char*)VLg + ((size_t)(h * 16 + nt1) << 14), 16384u, sbb + 8);
        }

        // ---- online softmax (exp2 domain)
        const bool diag = (kt == qt);
        float nm0 = m0, nm1 = m1;
        #pragma unroll
        for (int nt = 0; nt < 16; nt++) {
            #pragma unroll
            for (int j = 0; j < 4; j++) {
                float v = sc[nt][j] * SCL;
                if (diag) {
                    int col = nt * 8 + c2 + (j & 1);
                    int rowl = wq + r + (j >> 1) * 8;
                    if (col > rowl) v = -1e30f;
                }
                sc[nt][j] = v;
            }
            nm0 = fmaxf(nm0, fmaxf(sc[nt][0], sc[nt][1]));
            nm1 = fmaxf(nm1, fmaxf(sc[nt][2], sc[nt][3]));
        }
        #pragma unroll
        for (int off = 1; off <= 2; off <<= 1) {
            nm0 = fmaxf(nm0, __shfl_xor_sync(0xffffffffu, nm0, off));
            nm1 = fmaxf(nm1, __shfl_xor_sync(0xffffffffu, nm1, off));
        }
        float rs0 = 0.f, rs1 = 0.f;
        #pragma unroll
        for (int nt = 0; nt < 16; nt++) {
            sc[nt][0] = exp2f(sc[nt][0] - nm0);
            sc[nt][1] = exp2f(sc[nt][1] - nm0);
            sc[nt][2] = exp2f(sc[nt][2] - nm1);
            sc[nt][3] = exp2f(sc[nt][3] - nm1);
            rs0 += sc[nt][0] + sc[nt][1];
            rs1 += sc[nt][2] + sc[nt][3];
        }
        #pragma unroll
        for (int off = 1; off <= 2; off <<= 1) {
            rs0 += __shfl_xor_sync(0xffffffffu, rs0, off);
            rs1 += __shfl_xor_sync(0xffffffffu, rs1, off);
        }
        float cr0 = exp2f(m0 - nm0), cr1 = exp2f(m1 - nm1);
        l0 = l0 * cr0 + rs0; l1 = l1 * cr1 + rs1;
        m0 = nm0; m1 = nm1;
        #pragma unroll
        for (int i = 0; i < 8; i++) {
            o[i][0] *= cr0; o[i][1] *= cr0;
            o[i][2] *= cr1; o[i][3] *= cr1;
        }

        // ---- O += P V  (3-term, term-major)
        const uint32_t vbase = ((uint32_t)(kt & 1)) * 16384u;
        #pragma unroll
        for (int kc = 0; kc < 8; kc++) {
            uint32_t a_h[4], a_l[4];
            a_h[0] = pack_hilo(sc[2*kc][0],   sc[2*kc][1],   a_l[0]);
            a_h[1] = pack_hilo(sc[2*kc][2],   sc[2*kc][3],   a_l[1]);
            a_h[2] = pack_hilo(sc[2*kc+1][0], sc[2*kc+1][1], a_l[2]);
            a_h[3] = pack_hilo(sc[2*kc+1][2], sc[2*kc+1][3], a_l[3]);
            const uint32_t scol = (uint32_t)(kc * 16) + b_chk * 8u;
            const uint32_t sub = (scol >> 6) * 8192u;
            uint32_t bh[8][2], bl[8][2];
            #pragma unroll
            for (int p = 0; p < 4; p++) {
                uint32_t boff = sub + SWZ((uint32_t)(p * 16 + b_row) * 128u + (scol & 63u) * 2u);
                uint32_t rh[4], rl[4];
                ldsm_x4(rh, VH0 + vbase + boff);
                ldsm_x4(rl, VL0 + vbase + boff);
                bh[2*p][0]=rh[0]; bh[2*p][1]=rh[1]; bh[2*p+1][0]=rh[2]; bh[2*p+1][1]=rh[3];
                bl[2*p][0]=rl[0]; bl[2*p][1]=rl[1]; bl[2*p+1][0]=rl[2]; bl[2*p+1][1]=rl[3];
            }
            #pragma unroll
            for (int i = 0; i < 8; i++) mma_bf16(o[i], a_h, bh[i]);
            #pragma unroll
            for (int i = 0; i < 8; i++) mma_bf16(o[i], a_h, bl[i]);
            #pragma unroll
            for (int i = 0; i < 8; i++) mma_bf16(o[i], a_l, bh[i]);
        }
    }

    // ---- normalize + write ctx
    const float i0 = 1.f / l0, i1 = 1.f / l1;
    #pragma unroll
    for (int nt = 0; nt < 8; nt++) {
        const int col = h * DV + nt * 8 + c2;
        #pragma unroll
        for (int half = 0; half < 2; half++) {
            const int row = qt * 128 + wq + r + half * 8;
            float inv = half ? i1 : i0;
            float v0 = o[nt][half * 2 + 0] * inv;
            float v1 = o[nt][half * 2 + 1] * inv;
            uint32_t pl;
            uint32_t ph = pack_hilo(v0, v1, pl);
            uint32_t inner = (uint32_t)(row & 127) * 128u + (uint32_t)(col & 63) * 2u;
            size_t off = (((size_t)(row >> 7) * KB_CTX + (col >> 6)) << 14) + SWZ(inner);
            *(uint32_t*)((char*)Ch + off) = ph;
            *(uint32_t*)((char*)Cl + off) = pl;
        }
    }
}

// ---------------------------------------------------------------- launch
extern "C" void kernel_launch(void* const* d_in, const int* in_sizes, int n_in,
                              void* d_out, int out_size)
{
    const int*   positions = (const int*)  d_in[0];
    const float* hidden    = (const float*)d_in[1];
    const float* in_ln     = (const float*)d_in[2];
    const float* qw        = (const float*)d_in[3];
    const float* kva_w     = (const float*)d_in[4];
    const float* kvaln     = (const float*)d_in[5];
    const float* kvb_w     = (const float*)d_in[6];
    const float* ow        = (const float*)d_in[7];
    const float* postln    = (const float*)d_in[8];
    const float* gatew     = (const float*)d_in[9];
    const float* fc1w      = (const float*)d_in[10];
    const float* fc2w      = (const float*)d_in[11];
    float* out = (float*)d_out;

    float *sa, *qb, *ckv, *kvn, *kvv, *kpe, *x2, *mlp, *pr;
    cudaGetSymbolAddress((void**)&sa,  g_sa);
    cudaGetSymbolAddress((void**)&qb,  g_q);
    cudaGetSymbolAddress((void**)&ckv, g_ckv);
    cudaGetSymbolAddress((void**)&kvn, g_kvn);
    cudaGetSymbolAddress((void**)&kvv, g_kv);
    cudaGetSymbolAddress((void**)&kpe, g_kpe);
    cudaGetSymbolAddress((void**)&x2,  g_x2);
    cudaGetSymbolAddress((void**)&mlp, g_mlp);
    cudaGetSymbolAddress((void**)&pr,  g_pr);

    __nv_bfloat16 *sah,*sal,*kvnh,*kvnl,*mlph,*mlpl,*ctxh,*ctxl,*hbh,*hbl;
    __nv_bfloat16 *qwh,*qwl,*kvah,*kval,*kbwh,*kbwl,*owh,*owl,*f1h,*f1l,*f2h,*f2l;
    __nv_bfloat16 *qbh,*qbl,*kbh,*kbl,*vth,*vtl;
    cudaGetSymbolAddress((void**)&sah,  g_sa_h);  cudaGetSymbolAddress((void**)&sal,  g_sa_l);
    cudaGetSymbolAddress((void**)&kvnh, g_kvn_h); cudaGetSymbolAddress((void**)&kvnl, g_kvn_l);
    cudaGetSymbolAddress((void**)&mlph, g_mlp_h); cudaGetSymbolAddress((void**)&mlpl, g_mlp_l);
    cudaGetSymbolAddress((void**)&ctxh, g_ctx_h); cudaGetSymbolAddress((void**)&ctxl, g_ctx_l);
    cudaGetSymbolAddress((void**)&hbh,  g_hb_h);  cudaGetSymbolAddress((void**)&hbl,  g_hb_l);
    cudaGetSymbolAddress((void**)&qwh,  g_qw_h);  cudaGetSymbolAddress((void**)&qwl,  g_qw_l);
    cudaGetSymbolAddress((void**)&kvah, g_kva_h); cudaGetSymbolAddress((void**)&kval, g_kva_l);
    cudaGetSymbolAddress((void**)&kbwh, g_kbw_h); cudaGetSymbolAddress((void**)&kbwl, g_kbw_l);
    cudaGetSymbolAddress((void**)&owh,  g_ow_h);  cudaGetSymbolAddress((void**)&owl,  g_ow_l);
    cudaGetSymbolAddress((void**)&f1h,  g_f1_h);  cudaGetSymbolAddress((void**)&f1l,  g_f1_l);
    cudaGetSymbolAddress((void**)&f2h,  g_f2_h);  cudaGetSymbolAddress((void**)&f2l,  g_f2_l);
    cudaGetSymbolAddress((void**)&qbh,  g_qb_h);  cudaGetSymbolAddress((void**)&qbl,  g_qb_l);
    cudaGetSymbolAddress((void**)&kbh,  g_kb_h);  cudaGetSymbolAddress((void**)&kbl,  g_kb_l);
    cudaGetSymbolAddress((void**)&vth,  g_vt_h);  cudaGetSymbolAddress((void**)&vtl,  g_vt_l);

    cudaFuncSetAttribute(bgemm<0>, cudaFuncAttributeMaxDynamicSharedMemorySize, BG_SMEM);
    cudaFuncSetAttribute(bgemm<1>, cudaFuncAttributeMaxDynamicSharedMemorySize, BG_SMEM);
    cudaFuncSetAttribute(bgemm<2>, cudaFuncAttributeMaxDynamicSharedMemorySize, BG_SMEM);
    cudaFuncSetAttribute(attn_tc,  cudaFuncAttributeMaxDynamicSharedMemorySize, AT_SMEM);

    // weight converts -> blocked hi/lo
    cvt_blk_kernel<<<2048, 256>>>(qw,    qwh,  qwl,  H_DIM, H_DIM, H_DIM);
    cvt_blk_kernel<<<512,  256>>>(kva_w, kvah, kval, CKV_P, KVR + 64, H_DIM);
    cvt_blk_kernel<<<512,  256>>>(kvb_w, kbwh, kbwl, H_DIM, H_DIM, KVR);
    cvt_blk_kernel<<<1024, 256>>>(ow,    owh,  owl,  H_DIM, H_DIM, NHEAD * DV);
    cvt_blk_kernel<<<4096, 256>>>(fc1w,  f1h,  f1l,  NFC1, NFC1, H_DIM);
    cvt_fc2_blk_kernel<<<4096, 256>>>(fc2w, f2h, f2l);

    // 1. input RMSNorm
    rmsnorm_kernel<<<S_LEN, 256>>>(hidden, in_ln, sa, sah, sal, H_DIM, H_DIM, KB_H);
    // 2. q projection
    bgemm<0><<<dim3(8, 16), 256, BG_SMEM>>>(sah, sal, qwh, qwl, H_DIM, KB_H,
        qb, nullptr, nullptr, nullptr, 0);
    // 3. kv_a projection (padded N=512)
    bgemm<0><<<dim3(2, 16), 256, BG_SMEM>>>(sah, sal, kvah, kval, CKV_P, KB_H,
        ckv, nullptr, nullptr, nullptr, 0);
    // 4. kv RMSNorm
    rmsnorm_kernel<<<S_LEN, 256>>>(ckv, kvaln, kvn, kvnh, kvnl, KVR, CKV_P, KB_KVR);
    // 5. kv_b projection
    bgemm<0><<<dim3(8, 16), 256, BG_SMEM>>>(kvnh, kvnl, kbwh, kbwl, H_DIM, KB_KVR,
        kvv, nullptr, nullptr, nullptr, 0);
    // 6. RoPE
    rope_kernel<<<S_LEN, 256>>>(positions, qb, ckv, kpe);
    // 7. attention operand converts
    qk_cvt_kernel<<<S_LEN, 256>>>(qb, kvv, kpe, qbh, qbl, kbh, kbl);
    vt_cvt_kernel<<<dim3(S_LEN / 128, NHEAD), 256>>>(kvv, vth, vtl);
    // 8. tensor-core attention
    attn_tc<<<256, 256, AT_SMEM>>>(qbh, qbl, kbh, kbl, vth, vtl, ctxh, ctxl);
    // 9. o projection + residual
    bgemm<2><<<dim3(8, 16), 256, BG_SMEM>>>(ctxh, ctxl, owh, owl, H_DIM, KB_CTX,
        x2, hidden, nullptr, nullptr, 0);
    // 10. post RMSNorm
    rmsnorm_kernel<<<S_LEN, 256>>>(x2, postln, mlp, mlph, mlpl, H_DIM, H_DIM, KB_H);
    // 11. gate softmax
    gate_kernel<<<S_LEN, 256>>>(mlp, gatew, pr);
    // 12. fc1 + SiLU*probs
    bgemm<1><<<dim3(NFC1 / 256, 16), 256, BG_SMEM>>>(mlph, mlpl, f1h, f1l, NFC1, KB_H,
        nullptr, pr, hbh, hbl, KB_FC2);
    // 13. fc2 + residual -> out
    bgemm<2><<<dim3(8, 16), 256, BG_SMEM>>>(hbh, hbl, f2h, f2l, H_DIM, KB_FC2,
        out, x2, nullptr, nullptr, 0);
}

// round 7
// speedup vs baseline: 2.2095x; 2.2095x over previous
#include <cuda_runtime.h>
#include <cuda_fp16.h>
#include <math.h>
#include <stdint.h>

// ---------------------------------------------------------------- constants
#define S_LEN 2048
#define H_DIM 2048
#define NHEAD 16
#define DQK   128
#define DV    64
#define KVR   256
#define NEXP  8
#define INTER 1408
#define NFC1  (NEXP*INTER)   // 11264
#define CKV_P 512

#define KB_H    (H_DIM/64)      // 32
#define KB_KVR  (KVR/64)        // 4
#define KB_CTX  ((NHEAD*DV)/64) // 16
#define KB_FC2  (NFC1/64)       // 176

// ---------------------------------------------------------------- scratch (fp32)
__device__ float g_sa  [S_LEN*H_DIM];
__device__ float g_q   [S_LEN*H_DIM];
__device__ float g_ckv [S_LEN*CKV_P];
__device__ float g_kvn [S_LEN*KVR];
__device__ float g_kv  [S_LEN*H_DIM];
__device__ float g_kpe [S_LEN*64];
__device__ float g_x2  [S_LEN*H_DIM];
__device__ float g_mlp [S_LEN*H_DIM];
__device__ float g_pr  [S_LEN*NEXP];

// ---------------------------------------------------------------- scratch (blocked fp16)
__device__ __half g_sa_f [S_LEN*H_DIM];
__device__ __half g_kvn_f[S_LEN*KVR];
__device__ __half g_mlp_f[S_LEN*H_DIM];
__device__ __half g_ctx_f[S_LEN*NHEAD*DV];
__device__ __half g_hb_f [(size_t)S_LEN*NFC1];
__device__ __half g_qw_f [H_DIM*H_DIM];
__device__ __half g_kva_f[CKV_P*H_DIM];
__device__ __half g_kbw_f[H_DIM*KVR];
__device__ __half g_ow_f [H_DIM*NHEAD*DV];
__device__ __half g_f1_f [(size_t)NFC1*H_DIM];
__device__ __half g_f2_f [(size_t)H_DIM*NFC1];
__device__ __half g_qb_f [S_LEN*H_DIM];
__device__ __half g_kb_f [S_LEN*H_DIM];
__device__ __half g_vt_f [S_LEN*NHEAD*DV];

// ---------------------------------------------------------------- helpers
__device__ __forceinline__ uint32_t smem_u32(const void* p) {
    uint32_t a;
    asm("{ .reg .u64 t; cvta.to.shared.u64 t, %1; cvt.u32.u64 %0, t; }" : "=r"(a) : "l"(p));
    return a;
}
#define SWZ(off) ((off) ^ (((off) >> 3) & 0x70u))

__device__ __forceinline__ void ldsm_x4(uint32_t* r, uint32_t addr) {
    asm volatile("ldmatrix.sync.aligned.m8n8.x4.shared.b16 {%0,%1,%2,%3}, [%4];"
                 : "=r"(r[0]), "=r"(r[1]), "=r"(r[2]), "=r"(r[3]) : "r"(addr));
}
__device__ __forceinline__ void mma_fp16(float* c, const uint32_t* a, const uint32_t* b) {
    asm volatile("mma.sync.aligned.m16n8k16.row.col.f32.f16.f16.f32 "
                 "{%0,%1,%2,%3}, {%4,%5,%6,%7}, {%8,%9}, {%0,%1,%2,%3};"
                 : "+f"(c[0]), "+f"(c[1]), "+f"(c[2]), "+f"(c[3])
                 : "r"(a[0]), "r"(a[1]), "r"(a[2]), "r"(a[3]), "r"(b[0]), "r"(b[1]));
}
#define MBAR_INIT(a, c) asm volatile("mbarrier.init.shared.b64 [%0], %1;" :: "r"(a), "r"(c) : "memory")
#define MBAR_EXPECT(a, b) asm volatile("mbarrier.arrive.expect_tx.shared.b64 _, [%0], %1;" :: "r"(a), "r"(b) : "memory")
#define MBAR_WAIT(a, ph) do { \
    asm volatile("{\n\t.reg .pred P1;\n\tWL_%=:\n\t" \
        "mbarrier.try_wait.parity.acquire.cta.shared::cta.b64 P1, [%0], %1, 0x989680;\n\t" \
        "@P1 bra.uni WD_%=;\n\tbra.uni WL_%=;\n\tWD_%=:\n\t}" \
        :: "r"(a), "r"(ph) : "memory"); } while (0)
__device__ __forceinline__ void bulk_g2s(uint32_t dst, const void* src, uint32_t bytes, uint32_t mbar) {
    asm volatile("cp.async.bulk.shared::cluster.global.mbarrier::complete_tx::bytes [%0], [%1], %2, [%3];"
                 :: "r"(dst), "l"(src), "r"(bytes), "r"(mbar) : "memory");
}

__device__ __forceinline__ uint32_t pack2(float x, float y) {
    __half2 h = __floats2half2_rn(x, y);
    return *reinterpret_cast<uint32_t*>(&h);
}
__device__ __forceinline__ void cvt8(const float* v, uint4& p) {
    p = make_uint4(pack2(v[0], v[1]), pack2(v[2], v[3]), pack2(v[4], v[5]), pack2(v[6], v[7]));
}
__device__ __forceinline__ size_t blk_chunk_off(int blk_idx, int row, int c8) {
    uint32_t inner = (uint32_t)row * 128u + (uint32_t)c8 * 16u;
    return ((size_t)blk_idx << 14) + SWZ(inner);
}

// ---------------------------------------------------------------- weight converts
__global__ void cvt_blk_kernel(const float* __restrict__ src, __half* __restrict__ D,
                               int Npad, int Nreal, int K) {
    const int KC = K >> 3;
    const int KBk = K >> 6;
    const size_t tot = (size_t)Npad * KC;
    for (size_t idx = (size_t)blockIdx.x * blockDim.x + threadIdx.x; idx < tot;
         idx += (size_t)gridDim.x * blockDim.x) {
        int n = (int)(idx / KC), c = (int)(idx - (size_t)n * KC);
        float v[8];
        if (n < Nreal) {
            const float4 f0 = *(const float4*)(src + (size_t)n * K + c * 8);
            const float4 f1 = *(const float4*)(src + (size_t)n * K + c * 8 + 4);
            v[0]=f0.x; v[1]=f0.y; v[2]=f0.z; v[3]=f0.w; v[4]=f1.x; v[5]=f1.y; v[6]=f1.z; v[7]=f1.w;
        } else {
            #pragma unroll
            for (int j = 0; j < 8; j++) v[j] = 0.f;
        }
        uint4 p; cvt8(v, p);
        *(uint4*)((char*)D + blk_chunk_off((n >> 7) * KBk + (c >> 3), n & 127, c & 7)) = p;
    }
}

__global__ void cvt_fc2_blk_kernel(const float* __restrict__ w, __half* __restrict__ D) {
    const int KC = NFC1 >> 3;
    const size_t tot = (size_t)H_DIM * KC;
    for (size_t idx = (size_t)blockIdx.x * blockDim.x + threadIdx.x; idx < tot;
         idx += (size_t)gridDim.x * blockDim.x) {
        int n = (int)(idx / KC), c = (int)(idx - (size_t)n * KC);
        int k0 = c * 8;
        int e = k0 / INTER, i = k0 - e * INTER;
        const float* sp = w + ((size_t)e * H_DIM + n) * INTER + i;
        float v[8];
        const float4 f0 = *(const float4*)sp;
        const float4 f1 = *(const float4*)(sp + 4);
        v[0]=f0.x; v[1]=f0.y; v[2]=f0.z; v[3]=f0.w; v[4]=f1.x; v[5]=f1.y; v[6]=f1.z; v[7]=f1.w;
        uint4 p; cvt8(v, p);
        *(uint4*)((char*)D + blk_chunk_off((n >> 7) * KB_FC2 + (c >> 3), n & 127, c & 7)) = p;
    }
}

// ---------------------------------------------------------------- rmsnorm (+blocked fp16)
__global__ void rmsnorm_kernel(const float* __restrict__ x, const float* __restrict__ w,
                               float* __restrict__ y, __half* __restrict__ yf,
                               int W, int xs, int KBk)
{
    int s = blockIdx.x, tid = threadIdx.x;
    const float* xr = x + (size_t)s * xs;
    float ss = 0.f;
    for (int i = tid; i < W; i += 256) { float v = xr[i]; ss += v * v; }
    __shared__ float red[256];
    red[tid] = ss; __syncthreads();
    for (int o = 128; o > 0; o >>= 1) { if (tid < o) red[tid] += red[tid + o]; __syncthreads(); }
    float inv = rsqrtf(red[0] / (float)W + 1e-6f);
    float* yr = y + (size_t)s * W;
    const int KC = W >> 3;
    for (int c = tid; c < KC; c += 256) {
        float v[8];
        #pragma unroll
        for (int j = 0; j < 8; j++) {
            int i = c * 8 + j;
            v[j] = w[i] * xr[i] * inv;
            yr[i] = v[j];
        }
        uint4 p; cvt8(v, p);
        *(uint4*)((char*)yf + blk_chunk_off((s >> 7) * KBk + (c >> 3), s & 127, c & 7)) = p;
    }
}

// ---------------------------------------------------------------- rope
__global__ void rope_kernel(const int* __restrict__ positions,
                            float* __restrict__ q,
                            const float* __restrict__ ckv,
                            float* __restrict__ kpe)
{
    int s = blockIdx.x;
    float p = (float)positions[s];
    for (int idx = threadIdx.x; idx < NHEAD * 32 + 32; idx += blockDim.x) {
        int j = idx & 31;
        float ang = p * powf(10000.0f, -(float)j * (1.0f / 32.0f));
        float c = cosf(ang), sn = sinf(ang);
        if (idx < NHEAD * 32) {
            int hh = idx >> 5;
            float* xp = q + (size_t)s * H_DIM + hh * DQK + 64;
            float x0 = xp[j], x1 = xp[j + 32];
            xp[j]      = x0 * c - x1 * sn;
            xp[j + 32] = x1 * c + x0 * sn;
        } else {
            const float* xp = ckv + (size_t)s * CKV_P + 256;
            float x0 = xp[j], x1 = xp[j + 32];
            kpe[(size_t)s * 64 + j]      = x0 * c - x1 * sn;
            kpe[(size_t)s * 64 + j + 32] = x1 * c + x0 * sn;
        }
    }
}

// ---------------------------------------------------------------- gate softmax
__global__ void gate_kernel(const float* __restrict__ x, const float* __restrict__ w,
                            float* __restrict__ probs)
{
    int s = blockIdx.x;
    int warp = threadIdx.x >> 5, lane = threadIdx.x & 31;
    const float* xr = x + (size_t)s * H_DIM;
    const float* wr = w + (size_t)warp * H_DIM;
    float acc = 0.f;
    for (int i = lane; i < H_DIM; i += 32) acc += xr[i] * wr[i];
    #pragma unroll
    for (int o = 16; o; o >>= 1) acc += __shfl_xor_sync(0xffffffffu, acc, o);
    __shared__ float lg[8];
    if (lane == 0) lg[warp] = acc;
    __syncthreads();
    if (threadIdx.x == 0) {
        float mx = lg[0];
        #pragma unroll
        for (int e = 1; e < 8; e++) mx = fmaxf(mx, lg[e]);
        float sum = 0.f, ev[8];
        #pragma unroll
        for (int e = 0; e < 8; e++) { ev[e] = __expf(lg[e] - mx); sum += ev[e]; }
        float invs = 1.f / sum;
        #pragma unroll
        for (int e = 0; e < 8; e++) probs[(size_t)s * 8 + e] = ev[e] * invs;
    }
}

// ---------------------------------------------------------------- attention input converts
__global__ void qk_cvt_kernel(const float* __restrict__ q, const float* __restrict__ kv,
                              const float* __restrict__ kpe,
                              __half* __restrict__ Qf, __half* __restrict__ Kf)
{
    const int s = blockIdx.x, tid = threadIdx.x;
    const int h = tid >> 4, d = (tid & 15) * 8;
    const size_t off = ((size_t)((h * 16 + (s >> 7)) * 2 + (d >> 6)) << 14)
                       + SWZ((uint32_t)(s & 127) * 128u + (uint32_t)(d & 63) * 2u);
    {
        float v[8];
        #pragma unroll
        for (int j = 0; j < 8; j++) v[j] = q[(size_t)s * H_DIM + h * DQK + d + j];
        uint4 p; cvt8(v, p);
        *(uint4*)((char*)Qf + off) = p;
    }
    {
        float v[8];
        #pragma unroll
        for (int j = 0; j < 8; j++) {
            int dd = d + j;
            v[j] = (dd < 64) ? kv[(size_t)s * H_DIM + h * DQK + dd]
                             : kpe[(size_t)s * 64 + dd - 64];
        }
        uint4 p; cvt8(v, p);
        *(uint4*)((char*)Kf + off) = p;
    }
}

__global__ void vt_cvt_kernel(const float* __restrict__ kv, __half* __restrict__ Vf)
{
    __shared__ float vt[128][65];
    const int sb = blockIdx.x, h = blockIdx.y, tid = threadIdx.x;
    #pragma unroll
    for (int i = 0; i < 32; i++) {
        int idx = tid + i * 256;
        int r = idx >> 6, c = idx & 63;
        vt[r][c] = kv[(size_t)(sb * 128 + r) * H_DIM + h * DQK + 64 + c];
    }
    __syncthreads();
    #pragma unroll
    for (int i = 0; i < 4; i++) {
        int idx = tid + i * 256;
        int d = idx >> 4, s0 = (idx & 15) * 8;
        float v[8];
        #pragma unroll
        for (int j = 0; j < 8; j++) v[j] = vt[s0 + j][d];
        uint4 p; cvt8(v, p);
        size_t off = ((size_t)(h * 16 + sb) << 14) + (size_t)(s0 >> 6) * 8192u
                     + SWZ((uint32_t)d * 128u + (uint32_t)(s0 & 63) * 2u);
        *(uint4*)((char*)Vf + off) = p;
    }
}

// ---------------------------------------------------------------- fp16 bulk-copy GEMM
// Tile 128x256, BK=64, 3-stage cp.async.bulk pipeline, single-term fp16 MMA.
#define BG_STAGE_B  49152u               // A 16KB + B 2x16KB
#define BG_SMEM     (1024 + 3 * 49152)   // 148480
#define OFF_A 0u
#define OFF_B 16384u

template<int EPI>
__global__ __launch_bounds__(256, 1) void bgemm(
    const __half* __restrict__ Ab, const __half* __restrict__ Bb,
    int N, int KBk,
    float* __restrict__ C, const float* __restrict__ extra,
    __half* __restrict__ Cf, int CKB)
{
    extern __shared__ char smem[];
    const uint32_t sb = smem_u32(smem);
    const uint32_t tb = (sb + 1023u) & ~1023u;
    const int tid = threadIdx.x, wid = tid >> 5, lane = tid & 31;
    const int n0 = blockIdx.x * 256, m0 = blockIdx.y * 128;
    const int mb = blockIdx.y, nb0 = blockIdx.x * 2;
    const int wm = (wid >> 2) * 64;
    const int wn = (wid & 3) * 64;
    const uint32_t bsel = (uint32_t)(wn >> 7) * 16384u;
    const int brow0 = wn & 64;

    if (tid == 0) { MBAR_INIT(sb, 1); MBAR_INIT(sb + 8, 1); MBAR_INIT(sb + 16, 1); }
    __syncthreads();

    auto load_stage = [&](int t) {
        const int s = t % 3;
        const uint32_t mb_addr = sb + s * 8;
        const uint32_t st = tb + s * BG_STAGE_B;
        MBAR_EXPECT(mb_addr, BG_STAGE_B);
        bulk_g2s(st + OFF_A,          (const char*)Ab + (((size_t)mb * KBk + t) << 14), 16384u, mb_addr);
        bulk_g2s(st + OFF_B,          (const char*)Bb + (((size_t)nb0 * KBk + t) << 14), 16384u, mb_addr);
        bulk_g2s(st + OFF_B + 16384u, (const char*)Bb + (((size_t)(nb0 + 1) * KBk + t) << 14), 16384u, mb_addr);
    };

    if (tid == 0) {
        #pragma unroll
        for (int i = 0; i < 3; i++) if (i < KBk) load_stage(i);
    }

    float acc[4][8][4];
    #pragma unroll
    for (int i = 0; i < 4; i++)
        #pragma unroll
        for (int j = 0; j < 8; j++)
            #pragma unroll
            for (int k = 0; k < 4; k++) acc[i][j][k] = 0.f;

    const uint32_t a_row = lane & 15, a_chk = lane >> 4;
    const uint32_t b_row = ((lane >> 4) & 1) * 8 + (lane & 7);
    const uint32_t b_chk = (lane >> 3) & 1;

    for (int t = 0; t < KBk; t++) {
        const int s = t % 3;
        MBAR_WAIT(sb + s * 8, (t / 3) & 1);
        const uint32_t st = tb + s * BG_STAGE_B;

        #pragma unroll
        for (int ks = 0; ks < 4; ks++) {
            uint32_t a[4][4], b[8][2];
            #pragma unroll
            for (int mt = 0; mt < 4; mt++) {
                uint32_t off = SWZ((uint32_t)(wm + mt * 16 + a_row) * 128u + (ks * 2 + a_chk) * 16u);
                ldsm_x4(a[mt], st + OFF_A + off);
            }
            #pragma unroll
            for (int p = 0; p < 4; p++) {
                uint32_t off = SWZ((uint32_t)(brow0 + p * 16 + b_row) * 128u + (ks * 2 + b_chk) * 16u);
                uint32_t r[4];
                ldsm_x4(r, st + OFF_B + bsel + off);
                b[2*p][0]=r[0]; b[2*p][1]=r[1]; b[2*p+1][0]=r[2]; b[2*p+1][1]=r[3];
            }
            #pragma unroll
            for (int mt = 0; mt < 4; mt++)
                #pragma unroll
                for (int nt = 0; nt < 8; nt++)
                    mma_fp16(acc[mt][nt], a[mt], b[nt]);
        }
        __syncthreads();
        if (tid == 0 && t + 3 < KBk) load_stage(t + 3);
    }

    #pragma unroll
    for (int mt = 0; mt < 4; mt++) {
        #pragma unroll
        for (int half = 0; half < 2; half++) {
            const int row = m0 + wm + mt * 16 + half * 8 + (lane >> 2);
            #pragma unroll
            for (int nt = 0; nt < 8; nt++) {
                const int col = n0 + wn + nt * 8 + (lane & 3) * 2;
                float v0 = acc[mt][nt][half * 2 + 0];
                float v1 = acc[mt][nt][half * 2 + 1];
                if (EPI == 0) {
                    *(float2*)&C[(size_t)row * N + col] = make_float2(v0, v1);
                } else if (EPI == 2) {
                    const float2 e2 = *(const float2*)&extra[(size_t)row * N + col];
                    *(float2*)&C[(size_t)row * N + col] = make_float2(v0 + e2.x, v1 + e2.y);
                } else {
                    float pf = extra[(size_t)row * NEXP + (col / INTER)];
                    float s0 = v0 / (1.f + __expf(-v0)) * pf;
                    float s1 = v1 / (1.f + __expf(-v1)) * pf;
                    uint32_t inner = (uint32_t)(row & 127) * 128u + (uint32_t)(col & 63) * 2u;
                    size_t off = (((size_t)(row >> 7) * CKB + (col >> 6)) << 14) + SWZ(inner);
                    *(uint32_t*)((char*)Cf + off) = pack2(s0, s1);
                }
            }
        }
    }
}

// ---------------------------------------------------------------- fp16 tensor-core flash attention
#define AT_SMEM (1024 + 96 * 1024)

__global__ __launch_bounds__(256, 1) void attn_tc(
    const __half* __restrict__ Qg, const __half* __restrict__ Kg,
    const __half* __restrict__ Vg, __half* __restrict__ Cf)
{
    extern __shared__ char smem[];
    const uint32_t sbb = smem_u32(smem);
    const uint32_t tb = (sbb + 1023u) & ~1023u;
    const uint32_t QS = tb, KS = tb + 32768u, VS = tb + 65536u;  // V: 2 stages x 16KB

    const int tid = threadIdx.x, wid = tid >> 5, lane = tid & 31;
    const int idx = (int)gridDim.x - 1 - (int)blockIdx.x;
    const int qt = idx >> 4, h = idx & 15;
    const int wq = wid * 16;
    const int r = lane >> 2, c2 = (lane & 3) * 2;

    if (tid == 0) { MBAR_INIT(sbb, 1); MBAR_INIT(sbb + 8, 1); }
    __syncthreads();
    if (tid == 0) {
        MBAR_EXPECT(sbb, 32768u);
        bulk_g2s(QS, (const char*)Qg + ((size_t)(h * 16 + qt) << 15), 32768u, sbb);
        MBAR_EXPECT(sbb + 8, 49152u);
        bulk_g2s(KS, (const char*)Kg + ((size_t)(h * 16 + 0) << 15), 32768u, sbb + 8);
        bulk_g2s(VS, (const char*)Vg + ((size_t)(h * 16 + 0) << 14), 16384u, sbb + 8);
    }

    float sc[16][4];
    float o[8][4];
    #pragma unroll
    for (int i = 0; i < 8; i++)
        #pragma unroll
        for (int j = 0; j < 4; j++) o[i][j] = 0.f;
    float m0 = -1e30f, m1 = -1e30f, l0 = 0.f, l1 = 0.f;
    const float SCL = 0.08838834764831845f * 1.44269504088896f;

    const uint32_t a_row = lane & 15, a_chk = lane >> 4;
    const uint32_t b_row = ((lane >> 4) & 1) * 8 + (lane & 7);
    const uint32_t b_chk = (lane >> 3) & 1;

    for (int kt = 0; kt <= qt; kt++) {
        MBAR_WAIT(sbb + 8, kt & 1);
        if (kt == 0) MBAR_WAIT(sbb, 0);

        // ---- S = Q K^T
        #pragma unroll
        for (int nt = 0; nt < 16; nt++)
            #pragma unroll
            for (int j = 0; j < 4; j++) sc[nt][j] = 0.f;

        #pragma unroll
        for (int kc = 0; kc < 8; kc++) {
            const uint32_t db = (kc >> 2) * 16384u;
            const uint32_t acol = ((uint32_t)(kc * 16) + a_chk * 8u) & 63u;
            uint32_t a[4];
            ldsm_x4(a, QS + db + SWZ((uint32_t)(wq + a_row) * 128u + acol * 2u));
            const uint32_t bcol = ((uint32_t)(kc * 16) + b_chk * 8u) & 63u;
            #pragma unroll
            for (int p = 0; p < 8; p++) {
                uint32_t rr[4];
                ldsm_x4(rr, KS + db + SWZ((uint32_t)(p * 16 + b_row) * 128u + bcol * 2u));
                uint32_t b0[2] = {rr[0], rr[1]}, b1[2] = {rr[2], rr[3]};
                mma_fp16(sc[2*p],   a, b0);
                mma_fp16(sc[2*p+1], a, b1);
            }
        }
        __syncthreads();
        if (tid == 0 && kt < qt) {
            const int nt1 = kt + 1;
            MBAR_EXPECT(sbb + 8, 49152u);
            bulk_g2s(KS, (const char*)Kg + ((size_t)(h * 16 + nt1) << 15), 32768u, sbb + 8);
            bulk_g2s(VS + ((uint32_t)(nt1 & 1)) * 16384u,
                     (const char*)Vg + ((size_t)(h * 16 + nt1) << 14), 16384u, sbb + 8);
        }

        // ---- online softmax (exp2 domain)
        const bool diag = (kt == qt);
        float nm0 = m0, nm1 = m1;
        #pragma unroll
        for (int nt = 0; nt < 16; nt++) {
            #pragma unroll
            for (int j = 0; j < 4; j++) {
                float v = sc[nt][j] * SCL;
                if (diag) {
                    int col = nt * 8 + c2 + (j & 1);
                    int rowl = wq + r + (j >> 1) * 8;
                    if (col > rowl) v = -1e30f;
                }
                sc[nt][j] = v;
            }
            nm0 = fmaxf(nm0, fmaxf(sc[nt][0], sc[nt][1]));
            nm1 = fmaxf(nm1, fmaxf(sc[nt][2], sc[nt][3]));
        }
        #pragma unroll
        for (int off = 1; off <= 2; off <<= 1) {
            nm0 = fmaxf(nm0, __shfl_xor_sync(0xffffffffu, nm0, off));
            nm1 = fmaxf(nm1, __shfl_xor_sync(0xffffffffu, nm1, off));
        }
        float rs0 = 0.f, rs1 = 0.f;
        #pragma unroll
        for (int nt = 0; nt < 16; nt++) {
            sc[nt][0] = exp2f(sc[nt][0] - nm0);
            sc[nt][1] = exp2f(sc[nt][1] - nm0);
            sc[nt][2] = exp2f(sc[nt][2] - nm1);
            sc[nt][3] = exp2f(sc[nt][3] - nm1);
            rs0 += sc[nt][0] + sc[nt][1];
            rs1 += sc[nt][2] + sc[nt][3];
        }
        #pragma unroll
        for (int off = 1; off <= 2; off <<= 1) {
            rs0 += __shfl_xor_sync(0xffffffffu, rs0, off);
            rs1 += __shfl_xor_sync(0xffffffffu, rs1, off);
        }
        float cr0 = exp2f(m0 - nm0), cr1 = exp2f(m1 - nm1);
        l0 = l0 * cr0 + rs0; l1 = l1 * cr1 + rs1;
        m0 = nm0; m1 = nm1;
        #pragma unroll
        for (int i = 0; i < 8; i++) {
            o[i][0] *= cr0; o[i][1] *= cr0;
            o[i][2] *= cr1; o[i][3] *= cr1;
        }

        // ---- O += P V
        const uint32_t vbase = VS + ((uint32_t)(kt & 1)) * 16384u;
        #pragma unroll
        for (int kc = 0; kc < 8; kc++) {
            uint32_t a[4];
            a[0] = pack2(sc[2*kc][0],   sc[2*kc][1]);
            a[1] = pack2(sc[2*kc][2],   sc[2*kc][3]);
            a[2] = pack2(sc[2*kc+1][0], sc[2*kc+1][1]);
            a[3] = pack2(sc[2*kc+1][2], sc[2*kc+1][3]);
            const uint32_t scol = (uint32_t)(kc * 16) + b_chk * 8u;
            const uint32_t sub = (scol >> 6) * 8192u;
            #pragma unroll
            for (int p = 0; p < 4; p++) {
                uint32_t rr[4];
                ldsm_x4(rr, vbase + sub + SWZ((uint32_t)(p * 16 + b_row) * 128u + (scol & 63u) * 2u));
                uint32_t b0[2] = {rr[0], rr[1]}, b1[2] = {rr[2], rr[3]};
                mma_fp16(o[2*p],   a, b0);
                mma_fp16(o[2*p+1], a, b1);
            }
        }
    }

    // ---- normalize + write ctx (blocked fp16)
    const float i0 = 1.f / l0, i1 = 1.f / l1;
    #pragma unroll
    for (int nt = 0; nt < 8; nt++) {
        const int col = h * DV + nt * 8 + c2;
        #pragma unroll
        for (int half = 0; half < 2; half++) {
            const int row = qt * 128 + wq + r + half * 8;
            float inv = half ? i1 : i0;
            float v0 = o[nt][half * 2 + 0] * inv;
            float v1 = o[nt][half * 2 + 1] * inv;
            uint32_t inner = (uint32_t)(row & 127) * 128u + (uint32_t)(col & 63) * 2u;
            size_t off = (((size_t)(row >> 7) * KB_CTX + (col >> 6)) << 14) + SWZ(inner);
            *(uint32_t*)((char*)Cf + off) = pack2(v0, v1);
        }
    }
}

// ---------------------------------------------------------------- launch
extern "C" void kernel_launch(void* const* d_in, const int* in_sizes, int n_in,
                              void* d_out, int out_size)
{
    const int*   positions = (const int*)  d_in[0];
    const float* hidden    = (const float*)d_in[1];
    const float* in_ln     = (const float*)d_in[2];
    const float* qw        = (const float*)d_in[3];
    const float* kva_w     = (const float*)d_in[4];
    const float* kvaln     = (const float*)d_in[5];
    const float* kvb_w     = (const float*)d_in[6];
    const float* ow        = (const float*)d_in[7];
    const float* postln    = (const float*)d_in[8];
    const float* gatew     = (const float*)d_in[9];
    const float* fc1w      = (const float*)d_in[10];
    const float* fc2w      = (const float*)d_in[11];
    float* out = (float*)d_out;

    float *sa, *qb, *ckv, *kvn, *kvv, *kpe, *x2, *mlp, *pr;
    cudaGetSymbolAddress((void**)&sa,  g_sa);
    cudaGetSymbolAddress((void**)&qb,  g_q);
    cudaGetSymbolAddress((void**)&ckv, g_ckv);
    cudaGetSymbolAddress((void**)&kvn, g_kvn);
    cudaGetSymbolAddress((void**)&kvv, g_kv);
    cudaGetSymbolAddress((void**)&kpe, g_kpe);
    cudaGetSymbolAddress((void**)&x2,  g_x2);
    cudaGetSymbolAddress((void**)&mlp, g_mlp);
    cudaGetSymbolAddress((void**)&pr,  g_pr);

    __half *saf,*kvnf,*mlpf,*ctxf,*hbf,*qwf,*kvaf,*kbwf,*owf,*f1f,*f2f,*qbf,*kbf,*vtf;
    cudaGetSymbolAddress((void**)&saf,  g_sa_f);
    cudaGetSymbolAddress((void**)&kvnf, g_kvn_f);
    cudaGetSymbolAddress((void**)&mlpf, g_mlp_f);
    cudaGetSymbolAddress((void**)&ctxf, g_ctx_f);
    cudaGetSymbolAddress((void**)&hbf,  g_hb_f);
    cudaGetSymbolAddress((void**)&qwf,  g_qw_f);
    cudaGetSymbolAddress((void**)&kvaf, g_kva_f);
    cudaGetSymbolAddress((void**)&kbwf, g_kbw_f);
    cudaGetSymbolAddress((void**)&owf,  g_ow_f);
    cudaGetSymbolAddress((void**)&f1f,  g_f1_f);
    cudaGetSymbolAddress((void**)&f2f,  g_f2_f);
    cudaGetSymbolAddress((void**)&qbf,  g_qb_f);
    cudaGetSymbolAddress((void**)&kbf,  g_kb_f);
    cudaGetSymbolAddress((void**)&vtf,  g_vt_f);

    cudaFuncSetAttribute(bgemm<0>, cudaFuncAttributeMaxDynamicSharedMemorySize, BG_SMEM);
    cudaFuncSetAttribute(bgemm<1>, cudaFuncAttributeMaxDynamicSharedMemorySize, BG_SMEM);
    cudaFuncSetAttribute(bgemm<2>, cudaFuncAttributeMaxDynamicSharedMemorySize, BG_SMEM);
    cudaFuncSetAttribute(attn_tc,  cudaFuncAttributeMaxDynamicSharedMemorySize, AT_SMEM);

    // weight converts -> blocked fp16
    cvt_blk_kernel<<<2048, 256>>>(qw,    qwf,  H_DIM, H_DIM, H_DIM);
    cvt_blk_kernel<<<512,  256>>>(kva_w, kvaf, CKV_P, KVR + 64, H_DIM);
    cvt_blk_kernel<<<512,  256>>>(kvb_w, kbwf, H_DIM, H_DIM, KVR);
    cvt_blk_kernel<<<1024, 256>>>(ow,    owf,  H_DIM, H_DIM, NHEAD * DV);
    cvt_blk_kernel<<<4096, 256>>>(fc1w,  f1f,  NFC1, NFC1, H_DIM);
    cvt_fc2_blk_kernel<<<4096, 256>>>(fc2w, f2f);

    // 1. input RMSNorm
    rmsnorm_kernel<<<S_LEN, 256>>>(hidden, in_ln, sa, saf, H_DIM, H_DIM, KB_H);
    // 2. q projection
    bgemm<0><<<dim3(8, 16), 256, BG_SMEM>>>(saf, qwf, H_DIM, KB_H,
        qb, nullptr, nullptr, 0);
    // 3. kv_a projection (padded N=512)
    bgemm<0><<<dim3(2, 16), 256, BG_SMEM>>>(saf, kvaf, CKV_P, KB_H,
        ckv, nullptr, nullptr, 0);
    // 4. kv RMSNorm
    rmsnorm_kernel<<<S_LEN, 256>>>(ckv, kvaln, kvn, kvnf, KVR, CKV_P, KB_KVR);
    // 5. kv_b projection
    bgemm<0><<<dim3(8, 16), 256, BG_SMEM>>>(kvnf, kbwf, H_DIM, KB_KVR,
        kvv, nullptr, nullptr, 0);
    // 6. RoPE
    rope_kernel<<<S_LEN, 256>>>(positions, qb, ckv, kpe);
    // 7. attention operand converts
    qk_cvt_kernel<<<S_LEN, 256>>>(qb, kvv, kpe, qbf, kbf);
    vt_cvt_kernel<<<dim3(S_LEN / 128, NHEAD), 256>>>(kvv, vtf);
    // 8. tensor-core attention
    attn_tc<<<256, 256, AT_SMEM>>>(qbf, kbf, vtf, ctxf);
    // 9. o projection + residual
    bgemm<2><<<dim3(8, 16), 256, BG_SMEM>>>(ctxf, owf, H_DIM, KB_CTX,
        x2, hidden, nullptr, 0);
    // 10. post RMSNorm
    rmsnorm_kernel<<<S_LEN, 256>>>(x2, postln, mlp, mlpf, H_DIM, H_DIM, KB_H);
    // 11. gate softmax
    gate_kernel<<<S_LEN, 256>>>(mlp, gatew, pr);
    // 12. fc1 + SiLU*probs -> blocked fp16 h
    bgemm<1><<<dim3(NFC1 / 256, 16), 256, BG_SMEM>>>(mlpf, f1f, NFC1, KB_H,
        nullptr, pr, hbf, KB_FC2);
    // 13. fc2 + residual -> out
    bgemm<2><<<dim3(8, 16), 256, BG_SMEM>>>(hbf, f2f, H_DIM, KB_FC2,
        out, x2, nullptr, 0);
}

// round 8
// speedup vs baseline: 2.2886x; 1.0358x over previous
#include <cuda_runtime.h>
#include <cuda_fp16.h>
#include <math.h>
#include <stdint.h>

// ---------------------------------------------------------------- constants
#define S_LEN 2048
#define H_DIM 2048
#define NHEAD 16
#define DQK   128
#define DV    64
#define KVR   256
#define NEXP  8
#define INTER 1408
#define NFC1  (NEXP*INTER)   // 11264
#define CKV_P 512

#define KB_H    (H_DIM/64)      // 32
#define KB_KVR  (KVR/64)        // 4
#define KB_CTX  ((NHEAD*DV)/64) // 16
#define KB_FC2  (NFC1/64)       // 176

// ---------------------------------------------------------------- scratch (fp32)
__device__ float g_sa  [S_LEN*H_DIM];
__device__ float g_q   [S_LEN*H_DIM];
__device__ float g_ckv [S_LEN*CKV_P];
__device__ float g_kvn [S_LEN*KVR];
__device__ float g_kv  [S_LEN*H_DIM];
__device__ float g_kpe [S_LEN*64];
__device__ float g_x2  [S_LEN*H_DIM];
__device__ float g_mlp [S_LEN*H_DIM];
__device__ float g_pr  [S_LEN*NEXP];

// ---------------------------------------------------------------- scratch (blocked fp16)
__device__ __half g_sa_f [S_LEN*H_DIM];
__device__ __half g_kvn_f[S_LEN*KVR];
__device__ __half g_mlp_f[S_LEN*H_DIM];
__device__ __half g_ctx_f[S_LEN*NHEAD*DV];
__device__ __half g_hb_f [(size_t)S_LEN*NFC1];
__device__ __half g_qw_f [H_DIM*H_DIM];
__device__ __half g_kva_f[CKV_P*H_DIM];
__device__ __half g_kbw_f[H_DIM*KVR];
__device__ __half g_ow_f [H_DIM*NHEAD*DV];
__device__ __half g_f1_f [(size_t)NFC1*H_DIM];
__device__ __half g_f2_f [(size_t)H_DIM*NFC1];
__device__ __half g_qb_f [S_LEN*H_DIM];
__device__ __half g_kb_f [S_LEN*H_DIM];
__device__ __half g_vt_f [S_LEN*NHEAD*DV];

// ---------------------------------------------------------------- helpers
__device__ __forceinline__ uint32_t smem_u32(const void* p) {
    uint32_t a;
    asm("{ .reg .u64 t; cvta.to.shared.u64 t, %1; cvt.u32.u64 %0, t; }" : "=r"(a) : "l"(p));
    return a;
}
#define SWZ(off) ((off) ^ (((off) >> 3) & 0x70u))

__device__ __forceinline__ void ldsm_x4(uint32_t* r, uint32_t addr) {
    asm volatile("ldmatrix.sync.aligned.m8n8.x4.shared.b16 {%0,%1,%2,%3}, [%4];"
                 : "=r"(r[0]), "=r"(r[1]), "=r"(r[2]), "=r"(r[3]) : "r"(addr));
}
__device__ __forceinline__ void mma_fp16(float* c, const uint32_t* a, const uint32_t* b) {
    asm volatile("mma.sync.aligned.m16n8k16.row.col.f32.f16.f16.f32 "
                 "{%0,%1,%2,%3}, {%4,%5,%6,%7}, {%8,%9}, {%0,%1,%2,%3};"
                 : "+f"(c[0]), "+f"(c[1]), "+f"(c[2]), "+f"(c[3])
                 : "r"(a[0]), "r"(a[1]), "r"(a[2]), "r"(a[3]), "r"(b[0]), "r"(b[1]));
}
#define MBAR_INIT(a, c) asm volatile("mbarrier.init.shared.b64 [%0], %1;" :: "r"(a), "r"(c) : "memory")
#define MBAR_EXPECT(a, b) asm volatile("mbarrier.arrive.expect_tx.shared.b64 _, [%0], %1;" :: "r"(a), "r"(b) : "memory")
#define MBAR_WAIT(a, ph) do { \
    asm volatile("{\n\t.reg .pred P1;\n\tWL_%=:\n\t" \
        "mbarrier.try_wait.parity.acquire.cta.shared::cta.b64 P1, [%0], %1, 0x989680;\n\t" \
        "@P1 bra.uni WD_%=;\n\tbra.uni WL_%=;\n\tWD_%=:\n\t}" \
        :: "r"(a), "r"(ph) : "memory"); } while (0)
__device__ __forceinline__ void bulk_g2s(uint32_t dst, const void* src, uint32_t bytes, uint32_t mbar) {
    asm volatile("cp.async.bulk.shared::cluster.global.mbarrier::complete_tx::bytes [%0], [%1], %2, [%3];"
                 :: "r"(dst), "l"(src), "r"(bytes), "r"(mbar) : "memory");
}

__device__ __forceinline__ uint32_t pack2(float x, float y) {
    __half2 h = __floats2half2_rn(x, y);
    return *reinterpret_cast<uint32_t*>(&h);
}
__device__ __forceinline__ void cvt8(const float* v, uint4& p) {
    p = make_uint4(pack2(v[0], v[1]), pack2(v[2], v[3]), pack2(v[4], v[5]), pack2(v[6], v[7]));
}
__device__ __forceinline__ size_t blk_chunk_off(int blk_idx, int row, int c8) {
    uint32_t inner = (uint32_t)row * 128u + (uint32_t)c8 * 16u;
    return ((size_t)blk_idx << 14) + SWZ(inner);
}

// ---------------------------------------------------------------- weight converts
__global__ void cvt_blk_kernel(const float* __restrict__ src, __half* __restrict__ D,
                               int Npad, int Nreal, int K) {
    const int KC = K >> 3;
    const int KBk = K >> 6;
    const size_t tot = (size_t)Npad * KC;
    for (size_t idx = (size_t)blockIdx.x * blockDim.x + threadIdx.x; idx < tot;
         idx += (size_t)gridDim.x * blockDim.x) {
        int n = (int)(idx / KC), c = (int)(idx - (size_t)n * KC);
        float v[8];
        if (n < Nreal) {
            const float4 f0 = *(const float4*)(src + (size_t)n * K + c * 8);
            const float4 f1 = *(const float4*)(src + (size_t)n * K + c * 8 + 4);
            v[0]=f0.x; v[1]=f0.y; v[2]=f0.z; v[3]=f0.w; v[4]=f1.x; v[5]=f1.y; v[6]=f1.z; v[7]=f1.w;
        } else {
            #pragma unroll
            for (int j = 0; j < 8; j++) v[j] = 0.f;
        }
        uint4 p; cvt8(v, p);
        *(uint4*)((char*)D + blk_chunk_off((n >> 7) * KBk + (c >> 3), n & 127, c & 7)) = p;
    }
}

__global__ void cvt_fc2_blk_kernel(const float* __restrict__ w, __half* __restrict__ D) {
    const int KC = NFC1 >> 3;
    const size_t tot = (size_t)H_DIM * KC;
    for (size_t idx = (size_t)blockIdx.x * blockDim.x + threadIdx.x; idx < tot;
         idx += (size_t)gridDim.x * blockDim.x) {
        int n = (int)(idx / KC), c = (int)(idx - (size_t)n * KC);
        int k0 = c * 8;
        int e = k0 / INTER, i = k0 - e * INTER;
        const float* sp = w + ((size_t)e * H_DIM + n) * INTER + i;
        float v[8];
        const float4 f0 = *(const float4*)sp;
        const float4 f1 = *(const float4*)(sp + 4);
        v[0]=f0.x; v[1]=f0.y; v[2]=f0.z; v[3]=f0.w; v[4]=f1.x; v[5]=f1.y; v[6]=f1.z; v[7]=f1.w;
        uint4 p; cvt8(v, p);
        *(uint4*)((char*)D + blk_chunk_off((n >> 7) * KB_FC2 + (c >> 3), n & 127, c & 7)) = p;
    }
}

// ---------------------------------------------------------------- rmsnorm (+blocked fp16)
__global__ void rmsnorm_kernel(const float* __restrict__ x, const float* __restrict__ w,
                               float* __restrict__ y, __half* __restrict__ yf,
                               int W, int xs, int KBk)
{
    int s = blockIdx.x, tid = threadIdx.x;
    const float* xr = x + (size_t)s * xs;
    float ss = 0.f;
    for (int i = tid; i < W; i += 256) { float v = xr[i]; ss += v * v; }
    __shared__ float red[256];
    red[tid] = ss; __syncthreads();
    for (int o = 128; o > 0; o >>= 1) { if (tid < o) red[tid] += red[tid + o]; __syncthreads(); }
    float inv = rsqrtf(red[0] / (float)W + 1e-6f);
    float* yr = y + (size_t)s * W;
    const int KC = W >> 3;
    for (int c = tid; c < KC; c += 256) {
        float v[8];
        #pragma unroll
        for (int j = 0; j < 8; j++) {
            int i = c * 8 + j;
            v[j] = w[i] * xr[i] * inv;
            yr[i] = v[j];
        }
        uint4 p; cvt8(v, p);
        *(uint4*)((char*)yf + blk_chunk_off((s >> 7) * KBk + (c >> 3), s & 127, c & 7)) = p;
    }
}

// ---------------------------------------------------------------- rope
__global__ void rope_kernel(const int* __restrict__ positions,
                            float* __restrict__ q,
                            const float* __restrict__ ckv,
                            float* __restrict__ kpe)
{
    int s = blockIdx.x;
    float p = (float)positions[s];
    for (int idx = threadIdx.x; idx < NHEAD * 32 + 32; idx += blockDim.x) {
        int j = idx & 31;
        float ang = p * powf(10000.0f, -(float)j * (1.0f / 32.0f));
        float c = cosf(ang), sn = sinf(ang);
        if (idx < NHEAD * 32) {
            int hh = idx >> 5;
            float* xp = q + (size_t)s * H_DIM + hh * DQK + 64;
            float x0 = xp[j], x1 = xp[j + 32];
            xp[j]      = x0 * c - x1 * sn;
            xp[j + 32] = x1 * c + x0 * sn;
        } else {
            const float* xp = ckv + (size_t)s * CKV_P + 256;
            float x0 = xp[j], x1 = xp[j + 32];
            kpe[(size_t)s * 64 + j]      = x0 * c - x1 * sn;
            kpe[(size_t)s * 64 + j + 32] = x1 * c + x0 * sn;
        }
    }
}

// ---------------------------------------------------------------- gate softmax
__global__ void gate_kernel(const float* __restrict__ x, const float* __restrict__ w,
                            float* __restrict__ probs)
{
    int s = blockIdx.x;
    int warp = threadIdx.x >> 5, lane = threadIdx.x & 31;
    const float* xr = x + (size_t)s * H_DIM;
    const float* wr = w + (size_t)warp * H_DIM;
    float acc = 0.f;
    for (int i = lane; i < H_DIM; i += 32) acc += xr[i] * wr[i];
    #pragma unroll
    for (int o = 16; o; o >>= 1) acc += __shfl_xor_sync(0xffffffffu, acc, o);
    __shared__ float lg[8];
    if (lane == 0) lg[warp] = acc;
    __syncthreads();
    if (threadIdx.x == 0) {
        float mx = lg[0];
        #pragma unroll
        for (int e = 1; e < 8; e++) mx = fmaxf(mx, lg[e]);
        float sum = 0.f, ev[8];
        #pragma unroll
        for (int e = 0; e < 8; e++) { ev[e] = __expf(lg[e] - mx); sum += ev[e]; }
        float invs = 1.f / sum;
        #pragma unroll
        for (int e = 0; e < 8; e++) probs[(size_t)s * 8 + e] = ev[e] * invs;
    }
}

// ---------------------------------------------------------------- attention input converts
__global__ void qk_cvt_kernel(const float* __restrict__ q, const float* __restrict__ kv,
                              const float* __restrict__ kpe,
                              __half* __restrict__ Qf, __half* __restrict__ Kf)
{
    const int s = blockIdx.x, tid = threadIdx.x;
    const int h = tid >> 4, d = (tid & 15) * 8;
    const size_t off = ((size_t)((h * 16 + (s >> 7)) * 2 + (d >> 6)) << 14)
                       + SWZ((uint32_t)(s & 127) * 128u + (uint32_t)(d & 63) * 2u);
    {
        float v[8];
        #pragma unroll
        for (int j = 0; j < 8; j++) v[j] = q[(size_t)s * H_DIM + h * DQK + d + j];
        uint4 p; cvt8(v, p);
        *(uint4*)((char*)Qf + off) = p;
    }
    {
        float v[8];
        #pragma unroll
        for (int j = 0; j < 8; j++) {
            int dd = d + j;
            v[j] = (dd < 64) ? kv[(size_t)s * H_DIM + h * DQK + dd]
                             : kpe[(size_t)s * 64 + dd - 64];
        }
        uint4 p; cvt8(v, p);
        *(uint4*)((char*)Kf + off) = p;
    }
}

__global__ void vt_cvt_kernel(const float* __restrict__ kv, __half* __restrict__ Vf)
{
    __shared__ float vt[128][65];
    const int sb = blockIdx.x, h = blockIdx.y, tid = threadIdx.x;
    #pragma unroll
    for (int i = 0; i < 32; i++) {
        int idx = tid + i * 256;
        int r = idx >> 6, c = idx & 63;
        vt[r][c] = kv[(size_t)(sb * 128 + r) * H_DIM + h * DQK + 64 + c];
    }
    __syncthreads();
    #pragma unroll
    for (int i = 0; i < 4; i++) {
        int idx = tid + i * 256;
        int d = idx >> 4, s0 = (idx & 15) * 8;
        float v[8];
        #pragma unroll
        for (int j = 0; j < 8; j++) v[j] = vt[s0 + j][d];
        uint4 p; cvt8(v, p);
        size_t off = ((size_t)(h * 16 + sb) << 14) + (size_t)(s0 >> 6) * 8192u
                     + SWZ((uint32_t)d * 128u + (uint32_t)(s0 & 63) * 2u);
        *(uint4*)((char*)Vf + off) = p;
    }
}

// ---------------------------------------------------------------- fp16 bulk-copy GEMM
// Tile 128x256, BK=64, 3-stage cp.async.bulk pipeline.
// Optional second (B,C) pair: blocks with blockIdx.x >= nbSplit use (Bb2, C2, N2).
#define BG_STAGE_B  49152u
#define BG_SMEM     (1024 + 3 * 49152)
#define OFF_A 0u
#define OFF_B 16384u

template<int EPI>
__global__ __launch_bounds__(256, 1) void bgemm(
    const __half* __restrict__ Ab, const __half* __restrict__ Bb,
    int N, int KBk,
    float* __restrict__ C, const float* __restrict__ extra,
    __half* __restrict__ Cf, int CKB,
    const __half* __restrict__ Bb2, float* __restrict__ C2, int nbSplit, int N2)
{
    extern __shared__ char smem[];
    const uint32_t sb = smem_u32(smem);
    const uint32_t tb = (sb + 1023u) & ~1023u;
    const int tid = threadIdx.x, wid = tid >> 5, lane = tid & 31;

    const __half* Buse = Bb;
    float* Cuse = C;
    int Nuse = N;
    int bx = blockIdx.x;
    if (Bb2 != nullptr && bx >= nbSplit) {
        Buse = Bb2; Cuse = C2; Nuse = N2; bx -= nbSplit;
    }
    const int n0 = bx * 256, m0 = blockIdx.y * 128;
    const int mb = blockIdx.y, nb0 = bx * 2;
    const int wm = (wid >> 2) * 64;
    const int wn = (wid & 3) * 64;
    const uint32_t bsel = (uint32_t)(wn >> 7) * 16384u;
    const int brow0 = wn & 64;

    if (tid == 0) { MBAR_INIT(sb, 1); MBAR_INIT(sb + 8, 1); MBAR_INIT(sb + 16, 1); }
    __syncthreads();

    auto load_stage = [&](int t) {
        const int s = t % 3;
        const uint32_t mb_addr = sb + s * 8;
        const uint32_t st = tb + s * BG_STAGE_B;
        MBAR_EXPECT(mb_addr, BG_STAGE_B);
        bulk_g2s(st + OFF_A,          (const char*)Ab   + (((size_t)mb * KBk + t) << 14), 16384u, mb_addr);
        bulk_g2s(st + OFF_B,          (const char*)Buse + (((size_t)nb0 * KBk + t) << 14), 16384u, mb_addr);
        bulk_g2s(st + OFF_B + 16384u, (const char*)Buse + (((size_t)(nb0 + 1) * KBk + t) << 14), 16384u, mb_addr);
    };

    if (tid == 0) {
        #pragma unroll
        for (int i = 0; i < 3; i++) if (i < KBk) load_stage(i);
    }

    float acc[4][8][4];
    #pragma unroll
    for (int i = 0; i < 4; i++)
        #pragma unroll
        for (int j = 0; j < 8; j++)
            #pragma unroll
            for (int k = 0; k < 4; k++) acc[i][j][k] = 0.f;

    const uint32_t a_row = lane & 15, a_chk = lane >> 4;
    const uint32_t b_row = ((lane >> 4) & 1) * 8 + (lane & 7);
    const uint32_t b_chk = (lane >> 3) & 1;

    for (int t = 0; t < KBk; t++) {
        const int s = t % 3;
        MBAR_WAIT(sb + s * 8, (t / 3) & 1);
        const uint32_t st = tb + s * BG_STAGE_B;

        #pragma unroll
        for (int ks = 0; ks < 4; ks++) {
            uint32_t a[4][4], b[8][2];
            #pragma unroll
            for (int mt = 0; mt < 4; mt++) {
                uint32_t off = SWZ((uint32_t)(wm + mt * 16 + a_row) * 128u + (ks * 2 + a_chk) * 16u);
                ldsm_x4(a[mt], st + OFF_A + off);
            }
            #pragma unroll
            for (int p = 0; p < 4; p++) {
                uint32_t off = SWZ((uint32_t)(brow0 + p * 16 + b_row) * 128u + (ks * 2 + b_chk) * 16u);
                uint32_t r[4];
                ldsm_x4(r, st + OFF_B + bsel + off);
                b[2*p][0]=r[0]; b[2*p][1]=r[1]; b[2*p+1][0]=r[2]; b[2*p+1][1]=r[3];
            }
            #pragma unroll
            for (int mt = 0; mt < 4; mt++)
                #pragma unroll
                for (int nt = 0; nt < 8; nt++)
                    mma_fp16(acc[mt][nt], a[mt], b[nt]);
        }
        __syncthreads();
        if (tid == 0 && t + 3 < KBk) load_stage(t + 3);
    }

    #pragma unroll
    for (int mt = 0; mt < 4; mt++) {
        #pragma unroll
        for (int half = 0; half < 2; half++) {
            const int row = m0 + wm + mt * 16 + half * 8 + (lane >> 2);
            #pragma unroll
            for (int nt = 0; nt < 8; nt++) {
                const int col = n0 + wn + nt * 8 + (lane & 3) * 2;
                float v0 = acc[mt][nt][half * 2 + 0];
                float v1 = acc[mt][nt][half * 2 + 1];
                if (EPI == 0) {
                    *(float2*)&Cuse[(size_t)row * Nuse + col] = make_float2(v0, v1);
                } else if (EPI == 2) {
                    const float2 e2 = *(const float2*)&extra[(size_t)row * Nuse + col];
                    *(float2*)&Cuse[(size_t)row * Nuse + col] = make_float2(v0 + e2.x, v1 + e2.y);
                } else {
                    float pf = extra[(size_t)row * NEXP + (col / INTER)];
                    float s0 = v0 / (1.f + __expf(-v0)) * pf;
                    float s1 = v1 / (1.f + __expf(-v1)) * pf;
                    uint32_t inner = (uint32_t)(row & 127) * 128u + (uint32_t)(col & 63) * 2u;
                    size_t off = (((size_t)(row >> 7) * CKB + (col >> 6)) << 14) + SWZ(inner);
                    *(uint32_t*)((char*)Cf + off) = pack2(s0, s1);
                }
            }
        }
    }
}

// ---------------------------------------------------------------- fp16 flash attention
#define AT_SMEM (1024 + 96 * 1024)

__global__ __launch_bounds__(256, 1) void attn_tc(
    const __half* __restrict__ Qg, const __half* __restrict__ Kg,
    const __half* __restrict__ Vg, __half* __restrict__ Cf)
{
    extern __shared__ char smem[];
    const uint32_t sbb = smem_u32(smem);
    const uint32_t tb = (sbb + 1023u) & ~1023u;
    const uint32_t QS = tb, KS = tb + 32768u, VS = tb + 65536u;

    const int tid = threadIdx.x, wid = tid >> 5, lane = tid & 31;
    const int idx = (int)gridDim.x - 1 - (int)blockIdx.x;
    const int qt = idx >> 4, h = idx & 15;
    const int wq = wid * 16;
    const int r = lane >> 2, c2 = (lane & 3) * 2;

    if (tid == 0) { MBAR_INIT(sbb, 1); MBAR_INIT(sbb + 8, 1); }
    __syncthreads();
    if (tid == 0) {
        MBAR_EXPECT(sbb, 32768u);
        bulk_g2s(QS, (const char*)Qg + ((size_t)(h * 16 + qt) << 15), 32768u, sbb);
        MBAR_EXPECT(sbb + 8, 49152u);
        bulk_g2s(KS, (const char*)Kg + ((size_t)(h * 16 + 0) << 15), 32768u, sbb + 8);
        bulk_g2s(VS, (const char*)Vg + ((size_t)(h * 16 + 0) << 14), 16384u, sbb + 8);
    }

    float sc[16][4];
    float o[8][4];
    #pragma unroll
    for (int i = 0; i < 8; i++)
        #pragma unroll
        for (int j = 0; j < 4; j++) o[i][j] = 0.f;
    float m0 = -1e30f, m1 = -1e30f, l0 = 0.f, l1 = 0.f;
    const float SCL = 0.08838834764831845f * 1.44269504088896f;

    const uint32_t a_row = lane & 15, a_chk = lane >> 4;
    const uint32_t b_row = ((lane >> 4) & 1) * 8 + (lane & 7);
    const uint32_t b_chk = (lane >> 3) & 1;

    for (int kt = 0; kt <= qt; kt++) {
        MBAR_WAIT(sbb + 8, kt & 1);
        if (kt == 0) MBAR_WAIT(sbb, 0);

        #pragma unroll
        for (int nt = 0; nt < 16; nt++)
            #pragma unroll
            for (int j = 0; j < 4; j++) sc[nt][j] = 0.f;

        #pragma unroll
        for (int kc = 0; kc < 8; kc++) {
            const uint32_t db = (kc >> 2) * 16384u;
            const uint32_t acol = ((uint32_t)(kc * 16) + a_chk * 8u) & 63u;
            uint32_t a[4];
            ldsm_x4(a, QS + db + SWZ((uint32_t)(wq + a_row) * 128u + acol * 2u));
            const uint32_t bcol = ((uint32_t)(kc * 16) + b_chk * 8u) & 63u;
            #pragma unroll
            for (int p = 0; p < 8; p++) {
                uint32_t rr[4];
                ldsm_x4(rr, KS + db + SWZ((uint32_t)(p * 16 + b_row) * 128u + bcol * 2u));
                uint32_t b0[2] = {rr[0], rr[1]}, b1[2] = {rr[2], rr[3]};
                mma_fp16(sc[2*p],   a, b0);
                mma_fp16(sc[2*p+1], a, b1);
            }
        }
        __syncthreads();
        if (tid == 0 && kt < qt) {
            const int nt1 = kt + 1;
            MBAR_EXPECT(sbb + 8, 49152u);
            bulk_g2s(KS, (const char*)Kg + ((size_t)(h * 16 + nt1) << 15), 32768u, sbb + 8);
            bulk_g2s(VS + ((uint32_t)(nt1 & 1)) * 16384u,
                     (const char*)Vg + ((size_t)(h * 16 + nt1) << 14), 16384u, sbb + 8);
        }

        const bool diag = (kt == qt);
        float nm0 = m0, nm1 = m1;
        #pragma unroll
        for (int nt = 0; nt < 16; nt++) {
            #pragma unroll
            for (int j = 0; j < 4; j++) {
                float v = sc[nt][j] * SCL;
                if (diag) {
                    int col = nt * 8 + c2 + (j & 1);
                    int rowl = wq + r + (j >> 1) * 8;
                    if (col > rowl) v = -1e30f;
                }
                sc[nt][j] = v;
            }
            nm0 = fmaxf(nm0, fmaxf(sc[nt][0], sc[nt][1]));
            nm1 = fmaxf(nm1, fmaxf(sc[nt][2], sc[nt][3]));
        }
        #pragma unroll
        for (int off = 1; off <= 2; off <<= 1) {
            nm0 = fmaxf(nm0, __shfl_xor_sync(0xffffffffu, nm0, off));
            nm1 = fmaxf(nm1, __shfl_xor_sync(0xffffffffu, nm1, off));
        }
        float rs0 = 0.f, rs1 = 0.f;
        #pragma unroll
        for (int nt = 0; nt < 16; nt++) {
            sc[nt][0] = exp2f(sc[nt][0] - nm0);
            sc[nt][1] = exp2f(sc[nt][1] - nm0);
            sc[nt][2] = exp2f(sc[nt][2] - nm1);
            sc[nt][3] = exp2f(sc[nt][3] - nm1);
            rs0 += sc[nt][0] + sc[nt][1];
            rs1 += sc[nt][2] + sc[nt][3];
        }
        #pragma unroll
        for (int off = 1; off <= 2; off <<= 1) {
            rs0 += __shfl_xor_sync(0xffffffffu, rs0, off);
            rs1 += __shfl_xor_sync(0xffffffffu, rs1, off);
        }
        float cr0 = exp2f(m0 - nm0), cr1 = exp2f(m1 - nm1);
        l0 = l0 * cr0 + rs0; l1 = l1 * cr1 + rs1;
        m0 = nm0; m1 = nm1;
        #pragma unroll
        for (int i = 0; i < 8; i++) {
            o[i][0] *= cr0; o[i][1] *= cr0;
            o[i][2] *= cr1; o[i][3] *= cr1;
        }

        const uint32_t vbase = VS + ((uint32_t)(kt & 1)) * 16384u;
        #pragma unroll
        for (int kc = 0; kc < 8; kc++) {
            uint32_t a[4];
            a[0] = pack2(sc[2*kc][0],   sc[2*kc][1]);
            a[1] = pack2(sc[2*kc][2],   sc[2*kc][3]);
            a[2] = pack2(sc[2*kc+1][0], sc[2*kc+1][1]);
            a[3] = pack2(sc[2*kc+1][2], sc[2*kc+1][3]);
            const uint32_t scol = (uint32_t)(kc * 16) + b_chk * 8u;
            const uint32_t sub = (scol >> 6) * 8192u;
            #pragma unroll
            for (int p = 0; p < 4; p++) {
                uint32_t rr[4];
                ldsm_x4(rr, vbase + sub + SWZ((uint32_t)(p * 16 + b_row) * 128u + (scol & 63u) * 2u));
                uint32_t b0[2] = {rr[0], rr[1]}, b1[2] = {rr[2], rr[3]};
                mma_fp16(o[2*p],   a, b0);
                mma_fp16(o[2*p+1], a, b1);
            }
        }
    }

    const float i0 = 1.f / l0, i1 = 1.f / l1;
    #pragma unroll
    for (int nt = 0; nt < 8; nt++) {
        const int col = h * DV + nt * 8 + c2;
        #pragma unroll
        for (int half = 0; half < 2; half++) {
            const int row = qt * 128 + wq + r + half * 8;
            float inv = half ? i1 : i0;
            float v0 = o[nt][half * 2 + 0] * inv;
            float v1 = o[nt][half * 2 + 1] * inv;
            uint32_t inner = (uint32_t)(row & 127) * 128u + (uint32_t)(col & 63) * 2u;
            size_t off = (((size_t)(row >> 7) * KB_CTX + (col >> 6)) << 14) + SWZ(inner);
            *(uint32_t*)((char*)Cf + off) = pack2(v0, v1);
        }
    }
}

// ---------------------------------------------------------------- launch
extern "C" void kernel_launch(void* const* d_in, const int* in_sizes, int n_in,
                              void* d_out, int out_size)
{
    const int*   positions = (const int*)  d_in[0];
    const float* hidden    = (const float*)d_in[1];
    const float* in_ln     = (const float*)d_in[2];
    const float* qw        = (const float*)d_in[3];
    const float* kva_w     = (const float*)d_in[4];
    const float* kvaln     = (const float*)d_in[5];
    const float* kvb_w     = (const float*)d_in[6];
    const float* ow        = (const float*)d_in[7];
    const float* postln    = (const float*)d_in[8];
    const float* gatew     = (const float*)d_in[9];
    const float* fc1w      = (const float*)d_in[10];
    const float* fc2w      = (const float*)d_in[11];
    float* out = (float*)d_out;

    float *sa, *qb, *ckv, *kvn, *kvv, *kpe, *x2, *mlp, *pr;
    cudaGetSymbolAddress((void**)&sa,  g_sa);
    cudaGetSymbolAddress((void**)&qb,  g_q);
    cudaGetSymbolAddress((void**)&ckv, g_ckv);
    cudaGetSymbolAddress((void**)&kvn, g_kvn);
    cudaGetSymbolAddress((void**)&kvv, g_kv);
    cudaGetSymbolAddress((void**)&kpe, g_kpe);
    cudaGetSymbolAddress((void**)&x2,  g_x2);
    cudaGetSymbolAddress((void**)&mlp, g_mlp);
    cudaGetSymbolAddress((void**)&pr,  g_pr);

    __half *saf,*kvnf,*mlpf,*ctxf,*hbf,*qwf,*kvaf,*kbwf,*owf,*f1f,*f2f,*qbf,*kbf,*vtf;
    cudaGetSymbolAddress((void**)&saf,  g_sa_f);
    cudaGetSymbolAddress((void**)&kvnf, g_kvn_f);
    cudaGetSymbolAddress((void**)&mlpf, g_mlp_f);
    cudaGetSymbolAddress((void**)&ctxf, g_ctx_f);
    cudaGetSymbolAddress((void**)&hbf,  g_hb_f);
    cudaGetSymbolAddress((void**)&qwf,  g_qw_f);
    cudaGetSymbolAddress((void**)&kvaf, g_kva_f);
    cudaGetSymbolAddress((void**)&kbwf, g_kbw_f);
    cudaGetSymbolAddress((void**)&owf,  g_ow_f);
    cudaGetSymbolAddress((void**)&f1f,  g_f1_f);
    cudaGetSymbolAddress((void**)&f2f,  g_f2_f);
    cudaGetSymbolAddress((void**)&qbf,  g_qb_f);
    cudaGetSymbolAddress((void**)&kbf,  g_kb_f);
    cudaGetSymbolAddress((void**)&vtf,  g_vt_f);

    cudaFuncSetAttribute(bgemm<0>, cudaFuncAttributeMaxDynamicSharedMemorySize, BG_SMEM);
    cudaFuncSetAttribute(bgemm<1>, cudaFuncAttributeMaxDynamicSharedMemorySize, BG_SMEM);
    cudaFuncSetAttribute(bgemm<2>, cudaFuncAttributeMaxDynamicSharedMemorySize, BG_SMEM);
    cudaFuncSetAttribute(attn_tc,  cudaFuncAttributeMaxDynamicSharedMemorySize, AT_SMEM);

    // side stream + events (created once; capture-safe fork/join via events)
    static cudaStream_t s2 = nullptr;
    static cudaEvent_t evFork = nullptr, evQKA = nullptr, evKBW = nullptr,
                       evOW = nullptr, evF1 = nullptr, evF2 = nullptr;
    if (s2 == nullptr) {
        cudaStreamCreateWithFlags(&s2, cudaStreamNonBlocking);
        cudaEventCreateWithFlags(&evFork, cudaEventDisableTiming);
        cudaEventCreateWithFlags(&evQKA,  cudaEventDisableTiming);
        cudaEventCreateWithFlags(&evKBW,  cudaEventDisableTiming);
        cudaEventCreateWithFlags(&evOW,   cudaEventDisableTiming);
        cudaEventCreateWithFlags(&evF1,   cudaEventDisableTiming);
        cudaEventCreateWithFlags(&evF2,   cudaEventDisableTiming);
    }

    // fork: weight converts on s2, overlapping the main chain
    cudaEventRecord(evFork, 0);
    cudaStreamWaitEvent(s2, evFork, 0);
    cvt_blk_kernel<<<2048, 256, 0, s2>>>(qw,    qwf,  H_DIM, H_DIM, H_DIM);
    cvt_blk_kernel<<<512,  256, 0, s2>>>(kva_w, kvaf, CKV_P, KVR + 64, H_DIM);
    cudaEventRecord(evQKA, s2);
    cvt_blk_kernel<<<512,  256, 0, s2>>>(kvb_w, kbwf, H_DIM, H_DIM, KVR);
    cudaEventRecord(evKBW, s2);
    cvt_blk_kernel<<<1024, 256, 0, s2>>>(ow,    owf,  H_DIM, H_DIM, NHEAD * DV);
    cudaEventRecord(evOW, s2);
    cvt_blk_kernel<<<4096, 256, 0, s2>>>(fc1w,  f1f,  NFC1, NFC1, H_DIM);
    cudaEventRecord(evF1, s2);
    cvt_fc2_blk_kernel<<<4096, 256, 0, s2>>>(fc2w, f2f);
    cudaEventRecord(evF2, s2);

    // 1. input RMSNorm (main stream, overlaps converts)
    rmsnorm_kernel<<<S_LEN, 256>>>(hidden, in_ln, sa, saf, H_DIM, H_DIM, KB_H);
    // 2+3. merged q projection (blocks 0..7) + kv_a projection (blocks 8..9)
    cudaStreamWaitEvent(0, evQKA, 0);
    bgemm<0><<<dim3(10, 16), 256, BG_SMEM>>>(saf, qwf, H_DIM, KB_H,
        qb, nullptr, nullptr, 0, kvaf, ckv, 8, CKV_P);
    // 4. kv RMSNorm
    rmsnorm_kernel<<<S_LEN, 256>>>(ckv, kvaln, kvn, kvnf, KVR, CKV_P, KB_KVR);
    // 5. kv_b projection
    cudaStreamWaitEvent(0, evKBW, 0);
    bgemm<0><<<dim3(8, 16), 256, BG_SMEM>>>(kvnf, kbwf, H_DIM, KB_KVR,
        kvv, nullptr, nullptr, 0, nullptr, nullptr, 0, 0);
    // 6. RoPE
    rope_kernel<<<S_LEN, 256>>>(positions, qb, ckv, kpe);
    // 7. attention operand converts
    qk_cvt_kernel<<<S_LEN, 256>>>(qb, kvv, kpe, qbf, kbf);
    vt_cvt_kernel<<<dim3(S_LEN / 128, NHEAD), 256>>>(kvv, vtf);
    // 8. tensor-core attention
    attn_tc<<<256, 256, AT_SMEM>>>(qbf, kbf, vtf, ctxf);
    // 9. o projection + residual
    cudaStreamWaitEvent(0, evOW, 0);
    bgemm<2><<<dim3(8, 16), 256, BG_SMEM>>>(ctxf, owf, H_DIM, KB_CTX,
        x2, hidden, nullptr, 0, nullptr, nullptr, 0, 0);
    // 10. post RMSNorm
    rmsnorm_kernel<<<S_LEN, 256>>>(x2, postln, mlp, mlpf, H_DIM, H_DIM, KB_H);
    // 11. gate softmax
    gate_kernel<<<S_LEN, 256>>>(mlp, gatew, pr);
    // 12. fc1 + SiLU*probs
    cudaStreamWaitEvent(0, evF1, 0);
    bgemm<1><<<dim3(NFC1 / 256, 16), 256, BG_SMEM>>>(mlpf, f1f, NFC1, KB_H,
        nullptr, pr, hbf, KB_FC2, nullptr, nullptr, 0, 0);
    // 13. fc2 + residual -> out
    cudaStreamWaitEvent(0, evF2, 0);
    bgemm<2><<<dim3(8, 16), 256, BG_SMEM>>>(hbf, f2f, H_DIM, KB_FC2,
        out, x2, nullptr, 0, nullptr, nullptr, 0, 0);
}

// round 9
// speedup vs baseline: 2.5870x; 1.1304x over previous
#include <cuda_runtime.h>
#include <cuda_fp16.h>
#include <math.h>
#include <stdint.h>

// ---------------------------------------------------------------- constants
#define S_LEN 2048
#define H_DIM 2048
#define NHEAD 16
#define DQK   128
#define DV    64
#define KVR   256
#define NEXP  8
#define INTER 1408
#define NFC1  (NEXP*INTER)   // 11264
#define CKV_P 512

#define KB_H    (H_DIM/64)      // 32
#define KB_KVR  (KVR/64)        // 4
#define KB_CTX  ((NHEAD*DV)/64) // 16
#define KB_FC2  (NFC1/64)       // 176

// ---------------------------------------------------------------- scratch (fp32)
__device__ float g_sa  [S_LEN*H_DIM];
__device__ float g_q   [S_LEN*H_DIM];
__device__ float g_ckv [S_LEN*CKV_P];
__device__ float g_kvn [S_LEN*KVR];
__device__ float g_kv  [S_LEN*H_DIM];
__device__ float g_x2  [S_LEN*H_DIM];
__device__ float g_mlp [S_LEN*H_DIM];
__device__ float g_pr  [S_LEN*NEXP];

// ---------------------------------------------------------------- scratch (blocked fp16)
__device__ __half g_sa_f [S_LEN*H_DIM];
__device__ __half g_kvn_f[S_LEN*KVR];
__device__ __half g_mlp_f[S_LEN*H_DIM];
__device__ __half g_ctx_f[S_LEN*NHEAD*DV];
__device__ __half g_hb_f [(size_t)S_LEN*NFC1];
__device__ __half g_qw_f [H_DIM*H_DIM];
__device__ __half g_kva_f[CKV_P*H_DIM];
__device__ __half g_kbw_f[H_DIM*KVR];
__device__ __half g_ow_f [H_DIM*NHEAD*DV];
__device__ __half g_f1_f [(size_t)NFC1*H_DIM];
__device__ __half g_f2_f [(size_t)H_DIM*NFC1];
__device__ __half g_qb_f [S_LEN*H_DIM];
__device__ __half g_kb_f [S_LEN*H_DIM];
__device__ __half g_vt_f [S_LEN*NHEAD*DV];

// ---------------------------------------------------------------- helpers
__device__ __forceinline__ uint32_t smem_u32(const void* p) {
    uint32_t a;
    asm("{ .reg .u64 t; cvta.to.shared.u64 t, %1; cvt.u32.u64 %0, t; }" : "=r"(a) : "l"(p));
    return a;
}
#define SWZ(off) ((off) ^ (((off) >> 3) & 0x70u))

__device__ __forceinline__ void ldsm_x4(uint32_t* r, uint32_t addr) {
    asm volatile("ldmatrix.sync.aligned.m8n8.x4.shared.b16 {%0,%1,%2,%3}, [%4];"
                 : "=r"(r[0]), "=r"(r[1]), "=r"(r[2]), "=r"(r[3]) : "r"(addr));
}
__device__ __forceinline__ void mma_fp16(float* c, const uint32_t* a, const uint32_t* b) {
    asm volatile("mma.sync.aligned.m16n8k16.row.col.f32.f16.f16.f32 "
                 "{%0,%1,%2,%3}, {%4,%5,%6,%7}, {%8,%9}, {%0,%1,%2,%3};"
                 : "+f"(c[0]), "+f"(c[1]), "+f"(c[2]), "+f"(c[3])
                 : "r"(a[0]), "r"(a[1]), "r"(a[2]), "r"(a[3]), "r"(b[0]), "r"(b[1]));
}
#define MBAR_INIT(a, c) asm volatile("mbarrier.init.shared.b64 [%0], %1;" :: "r"(a), "r"(c) : "memory")
#define MBAR_EXPECT(a, b) asm volatile("mbarrier.arrive.expect_tx.shared.b64 _, [%0], %1;" :: "r"(a), "r"(b) : "memory")
#define MBAR_WAIT(a, ph) do { \
    asm volatile("{\n\t.reg .pred P1;\n\tWL_%=:\n\t" \
        "mbarrier.try_wait.parity.acquire.cta.shared::cta.b64 P1, [%0], %1, 0x989680;\n\t" \
        "@P1 bra.uni WD_%=;\n\tbra.uni WL_%=;\n\tWD_%=:\n\t}" \
        :: "r"(a), "r"(ph) : "memory"); } while (0)
__device__ __forceinline__ void bulk_g2s(uint32_t dst, const void* src, uint32_t bytes, uint32_t mbar) {
    asm volatile("cp.async.bulk.shared::cluster.global.mbarrier::complete_tx::bytes [%0], [%1], %2, [%3];"
                 :: "r"(dst), "l"(src), "r"(bytes), "r"(mbar) : "memory");
}

__device__ __forceinline__ uint32_t pack2(float x, float y) {
    __half2 h = __floats2half2_rn(x, y);
    return *reinterpret_cast<uint32_t*>(&h);
}
__device__ __forceinline__ void cvt8(const float* v, uint4& p) {
    p = make_uint4(pack2(v[0], v[1]), pack2(v[2], v[3]), pack2(v[4], v[5]), pack2(v[6], v[7]));
}
__device__ __forceinline__ size_t blk_chunk_off(int blk_idx, int row, int c8) {
    uint32_t inner = (uint32_t)row * 128u + (uint32_t)c8 * 16u;
    return ((size_t)blk_idx << 14) + SWZ(inner);
}

// ---------------------------------------------------------------- weight converts
__global__ void cvt_blk_kernel(const float* __restrict__ src, __half* __restrict__ D,
                               int Npad, int Nreal, int K) {
    const int KC = K >> 3;
    const int KBk = K >> 6;
    const size_t tot = (size_t)Npad * KC;
    for (size_t idx = (size_t)blockIdx.x * blockDim.x + threadIdx.x; idx < tot;
         idx += (size_t)gridDim.x * blockDim.x) {
        int n = (int)(idx / KC), c = (int)(idx - (size_t)n * KC);
        float v[8];
        if (n < Nreal) {
            const float4 f0 = *(const float4*)(src + (size_t)n * K + c * 8);
            const float4 f1 = *(const float4*)(src + (size_t)n * K + c * 8 + 4);
            v[0]=f0.x; v[1]=f0.y; v[2]=f0.z; v[3]=f0.w; v[4]=f1.x; v[5]=f1.y; v[6]=f1.z; v[7]=f1.w;
        } else {
            #pragma unroll
            for (int j = 0; j < 8; j++) v[j] = 0.f;
        }
        uint4 p; cvt8(v, p);
        *(uint4*)((char*)D + blk_chunk_off((n >> 7) * KBk + (c >> 3), n & 127, c & 7)) = p;
    }
}

__global__ void cvt_fc2_blk_kernel(const float* __restrict__ w, __half* __restrict__ D) {
    const int KC = NFC1 >> 3;
    const size_t tot = (size_t)H_DIM * KC;
    for (size_t idx = (size_t)blockIdx.x * blockDim.x + threadIdx.x; idx < tot;
         idx += (size_t)gridDim.x * blockDim.x) {
        int n = (int)(idx / KC), c = (int)(idx - (size_t)n * KC);
        int k0 = c * 8;
        int e = k0 / INTER, i = k0 - e * INTER;
        const float* sp = w + ((size_t)e * H_DIM + n) * INTER + i;
        float v[8];
        const float4 f0 = *(const float4*)sp;
        const float4 f1 = *(const float4*)(sp + 4);
        v[0]=f0.x; v[1]=f0.y; v[2]=f0.z; v[3]=f0.w; v[4]=f1.x; v[5]=f1.y; v[6]=f1.z; v[7]=f1.w;
        uint4 p; cvt8(v, p);
        *(uint4*)((char*)D + blk_chunk_off((n >> 7) * KB_FC2 + (c >> 3), n & 127, c & 7)) = p;
    }
}

// ---------------------------------------------------------------- rmsnorm (+blocked fp16)
__global__ void rmsnorm_kernel(const float* __restrict__ x, const float* __restrict__ w,
                               float* __restrict__ y, __half* __restrict__ yf,
                               int W, int xs, int KBk)
{
    int s = blockIdx.x, tid = threadIdx.x;
    const float* xr = x + (size_t)s * xs;
    float ss = 0.f;
    for (int i = tid; i < W; i += 256) { float v = xr[i]; ss += v * v; }
    __shared__ float red[256];
    red[tid] = ss; __syncthreads();
    for (int o = 128; o > 0; o >>= 1) { if (tid < o) red[tid] += red[tid + o]; __syncthreads(); }
    float inv = rsqrtf(red[0] / (float)W + 1e-6f);
    float* yr = y + (size_t)s * W;
    const int KC = W >> 3;
    for (int c = tid; c < KC; c += 256) {
        float v[8];
        #pragma unroll
        for (int j = 0; j < 8; j++) {
            int i = c * 8 + j;
            v[j] = w[i] * xr[i] * inv;
            yr[i] = v[j];
        }
        uint4 p; cvt8(v, p);
        *(uint4*)((char*)yf + blk_chunk_off((s >> 7) * KBk + (c >> 3), s & 127, c & 7)) = p;
    }
}

// ---------------------------------------------------------------- gate softmax
__global__ void gate_kernel(const float* __restrict__ x, const float* __restrict__ w,
                            float* __restrict__ probs)
{
    int s = blockIdx.x;
    int warp = threadIdx.x >> 5, lane = threadIdx.x & 31;
    const float* xr = x + (size_t)s * H_DIM;
    const float* wr = w + (size_t)warp * H_DIM;
    float acc = 0.f;
    for (int i = lane; i < H_DIM; i += 32) acc += xr[i] * wr[i];
    #pragma unroll
    for (int o = 16; o; o >>= 1) acc += __shfl_xor_sync(0xffffffffu, acc, o);
    __shared__ float lg[8];
    if (lane == 0) lg[warp] = acc;
    __syncthreads();
    if (threadIdx.x == 0) {
        float mx = lg[0];
        #pragma unroll
        for (int e = 1; e < 8; e++) mx = fmaxf(mx, lg[e]);
        float sum = 0.f, ev[8];
        #pragma unroll
        for (int e = 0; e < 8; e++) { ev[e] = __expf(lg[e] - mx); sum += ev[e]; }
        float invs = 1.f / sum;
        #pragma unroll
        for (int e = 0; e < 8; e++) probs[(size_t)s * 8 + e] = ev[e] * invs;
    }
}

// ---------------------------------------------------------------- fused rope + attention converts
// q raw (pre-rope) + kv + ckv -> head-blocked fp16 Q, K (rope applied inline)
__global__ void qk_cvt_kernel(const int* __restrict__ positions,
                              const float* __restrict__ q, const float* __restrict__ kv,
                              const float* __restrict__ ckv,
                              __half* __restrict__ Qf, __half* __restrict__ Kf)
{
    const int s = blockIdx.x, tid = threadIdx.x;
    const int h = tid >> 4, d = (tid & 15) * 8;
    const float p = (float)positions[s];
    const size_t off = ((size_t)((h * 16 + (s >> 7)) * 2 + (d >> 6)) << 14)
                       + SWZ((uint32_t)(s & 127) * 128u + (uint32_t)(d & 63) * 2u);
    // rope coefficients for this thread's 8 lanes (only used when d >= 64)
    float cs[8], sn[8];
    if (d >= 64) {
        #pragma unroll
        for (int j = 0; j < 8; j++) {
            int jj = (d - 64 + j) & 31;
            float ang = p * exp2f(-(float)jj * 0.41524101186092f); // log2(1e4)/32
            __sincosf(ang, &sn[j], &cs[j]);
        }
    }
    {
        const float* qr = q + (size_t)s * H_DIM + h * DQK;
        float v[8];
        #pragma unroll
        for (int j = 0; j < 8; j++) {
            int dd = d + j;
            if (dd < 64) v[j] = qr[dd];
            else if (dd < 96) v[j] = qr[dd] * cs[j] - qr[dd + 32] * sn[j];
            else             v[j] = qr[dd] * cs[j] + qr[dd - 32] * sn[j];
        }
        uint4 pk; cvt8(v, pk);
        *(uint4*)((char*)Qf + off) = pk;
    }
    {
        const float* kr = ckv + (size_t)s * CKV_P + 256 - 64;  // index by dd (>=64)
        const float* nr = kv + (size_t)s * H_DIM + h * DQK;
        float v[8];
        #pragma unroll
        for (int j = 0; j < 8; j++) {
            int dd = d + j;
            if (dd < 64) v[j] = nr[dd];
            else if (dd < 96) v[j] = kr[dd] * cs[j] - kr[dd + 32] * sn[j];
            else             v[j] = kr[dd] * cs[j] + kr[dd - 32] * sn[j];
        }
        uint4 pk; cvt8(v, pk);
        *(uint4*)((char*)Kf + off) = pk;
    }
}

__global__ void vt_cvt_kernel(const float* __restrict__ kv, __half* __restrict__ Vf)
{
    __shared__ float vt[128][65];
    const int sb = blockIdx.x, h = blockIdx.y, tid = threadIdx.x;
    #pragma unroll
    for (int i = 0; i < 32; i++) {
        int idx = tid + i * 256;
        int r = idx >> 6, c = idx & 63;
        vt[r][c] = kv[(size_t)(sb * 128 + r) * H_DIM + h * DQK + 64 + c];
    }
    __syncthreads();
    #pragma unroll
    for (int i = 0; i < 4; i++) {
        int idx = tid + i * 256;
        int dd = idx >> 4, s0 = (idx & 15) * 8;
        float v[8];
        #pragma unroll
        for (int j = 0; j < 8; j++) v[j] = vt[s0 + j][dd];
        uint4 p; cvt8(v, p);
        size_t off = ((size_t)(h * 16 + sb) << 14) + (size_t)(s0 >> 6) * 8192u
                     + SWZ((uint32_t)dd * 128u + (uint32_t)(s0 & 63) * 2u);
        *(uint4*)((char*)Vf + off) = p;
    }
}

// ---------------------------------------------------------------- fp16 bulk-copy GEMM
// Tile 128x128, BK=64, 3-stage pipeline, 2 CTAs/SM. Warp = 64x32.
#define BG_STAGE_B  32768u
#define BG_SMEM     (1024 + 3 * 32768)   // 99328
#define OFF_A 0u
#define OFF_B 16384u

template<int EPI>
__global__ __launch_bounds__(256, 2) void bgemm(
    const __half* __restrict__ Ab, const __half* __restrict__ Bb,
    int N, int KBk,
    float* __restrict__ C, const float* __restrict__ extra,
    __half* __restrict__ Cf, int CKB,
    const __half* __restrict__ Bb2, float* __restrict__ C2, int nbSplit, int N2)
{
    extern __shared__ char smem[];
    const uint32_t sb = smem_u32(smem);
    const uint32_t tb = (sb + 1023u) & ~1023u;
    const int tid = threadIdx.x, wid = tid >> 5, lane = tid & 31;

    const __half* Buse = Bb;
    float* Cuse = C;
    int Nuse = N;
    int bx = blockIdx.x;
    if (Bb2 != nullptr && bx >= nbSplit) {
        Buse = Bb2; Cuse = C2; Nuse = N2; bx -= nbSplit;
    }
    const int n0 = bx * 128, m0 = blockIdx.y * 128;
    const int mb = blockIdx.y, nb = bx;
    const int wm = (wid >> 2) * 64;
    const int wn = (wid & 3) * 32;

    if (tid == 0) { MBAR_INIT(sb, 1); MBAR_INIT(sb + 8, 1); MBAR_INIT(sb + 16, 1); }
    __syncthreads();

    auto load_stage = [&](int t) {
        const int s = t % 3;
        const uint32_t mb_addr = sb + s * 8;
        const uint32_t st = tb + s * BG_STAGE_B;
        MBAR_EXPECT(mb_addr, BG_STAGE_B);
        bulk_g2s(st + OFF_A, (const char*)Ab   + (((size_t)mb * KBk + t) << 14), 16384u, mb_addr);
        bulk_g2s(st + OFF_B, (const char*)Buse + (((size_t)nb * KBk + t) << 14), 16384u, mb_addr);
    };

    if (tid == 0) {
        #pragma unroll
        for (int i = 0; i < 3; i++) if (i < KBk) load_stage(i);
    }

    float acc[4][4][4];
    #pragma unroll
    for (int i = 0; i < 4; i++)
        #pragma unroll
        for (int j = 0; j < 4; j++)
            #pragma unroll
            for (int k = 0; k < 4; k++) acc[i][j][k] = 0.f;

    const uint32_t a_row = lane & 15, a_chk = lane >> 4;
    const uint32_t b_row = ((lane >> 4) & 1) * 8 + (lane & 7);
    const uint32_t b_chk = (lane >> 3) & 1;

    for (int t = 0; t < KBk; t++) {
        const int s = t % 3;
        MBAR_WAIT(sb + s * 8, (t / 3) & 1);
        const uint32_t st = tb + s * BG_STAGE_B;

        #pragma unroll
        for (int ks = 0; ks < 4; ks++) {
            uint32_t a[4][4], b[4][2];
            #pragma unroll
            for (int mt = 0; mt < 4; mt++) {
                uint32_t off = SWZ((uint32_t)(wm + mt * 16 + a_row) * 128u + (ks * 2 + a_chk) * 16u);
                ldsm_x4(a[mt], st + OFF_A + off);
            }
            #pragma unroll
            for (int p = 0; p < 2; p++) {
                uint32_t off = SWZ((uint32_t)(wn + p * 16 + b_row) * 128u + (ks * 2 + b_chk) * 16u);
                uint32_t r[4];
                ldsm_x4(r, st + OFF_B + off);
                b[2*p][0]=r[0]; b[2*p][1]=r[1]; b[2*p+1][0]=r[2]; b[2*p+1][1]=r[3];
            }
            #pragma unroll
            for (int mt = 0; mt < 4; mt++)
                #pragma unroll
                for (int nt = 0; nt < 4; nt++)
                    mma_fp16(acc[mt][nt], a[mt], b[nt]);
        }
        __syncthreads();
        if (tid == 0 && t + 3 < KBk) load_stage(t + 3);
    }

    #pragma unroll
    for (int mt = 0; mt < 4; mt++) {
        #pragma unroll
        for (int half = 0; half < 2; half++) {
            const int row = m0 + wm + mt * 16 + half * 8 + (lane >> 2);
            #pragma unroll
            for (int nt = 0; nt < 4; nt++) {
                const int col = n0 + wn + nt * 8 + (lane & 3) * 2;
                float v0 = acc[mt][nt][half * 2 + 0];
                float v1 = acc[mt][nt][half * 2 + 1];
                if (EPI == 0) {
                    *(float2*)&Cuse[(size_t)row * Nuse + col] = make_float2(v0, v1);
                } else if (EPI == 2) {
                    const float2 e2 = *(const float2*)&extra[(size_t)row * Nuse + col];
                    *(float2*)&Cuse[(size_t)row * Nuse + col] = make_float2(v0 + e2.x, v1 + e2.y);
                } else {
                    float pf = extra[(size_t)row * NEXP + (col / INTER)];
                    float s0 = v0 / (1.f + __expf(-v0)) * pf;
                    float s1 = v1 / (1.f + __expf(-v1)) * pf;
                    uint32_t inner = (uint32_t)(row & 127) * 128u + (uint32_t)(col & 63) * 2u;
                    size_t off = (((size_t)(row >> 7) * CKB + (col >> 6)) << 14) + SWZ(inner);
                    *(uint32_t*)((char*)Cf + off) = pack2(s0, s1);
                }
            }
        }
    }
}

// ---------------------------------------------------------------- fp16 flash attention
#define AT_SMEM (1024 + 96 * 1024)

__global__ __launch_bounds__(256, 1) void attn_tc(
    const __half* __restrict__ Qg, const __half* __restrict__ Kg,
    const __half* __restrict__ Vg, __half* __restrict__ Cf)
{
    extern __shared__ char smem[];
    const uint32_t sbb = smem_u32(smem);
    const uint32_t tb = (sbb + 1023u) & ~1023u;
    const uint32_t QS = tb, KS = tb + 32768u, VS = tb + 65536u;

    const int tid = threadIdx.x, wid = tid >> 5, lane = tid & 31;
    const int idx = (int)gridDim.x - 1 - (int)blockIdx.x;
    const int qt = idx >> 4, h = idx & 15;
    const int wq = wid * 16;
    const int r = lane >> 2, c2 = (lane & 3) * 2;

    if (tid == 0) { MBAR_INIT(sbb, 1); MBAR_INIT(sbb + 8, 1); }
    __syncthreads();
    if (tid == 0) {
        MBAR_EXPECT(sbb, 32768u);
        bulk_g2s(QS, (const char*)Qg + ((size_t)(h * 16 + qt) << 15), 32768u, sbb);
        MBAR_EXPECT(sbb + 8, 49152u);
        bulk_g2s(KS, (const char*)Kg + ((size_t)(h * 16 + 0) << 15), 32768u, sbb + 8);
        bulk_g2s(VS, (const char*)Vg + ((size_t)(h * 16 + 0) << 14), 16384u, sbb + 8);
    }

    float sc[16][4];
    float o[8][4];
    #pragma unroll
    for (int i = 0; i < 8; i++)
        #pragma unroll
        for (int j = 0; j < 4; j++) o[i][j] = 0.f;
    float m0 = -1e30f, m1 = -1e30f, l0 = 0.f, l1 = 0.f;
    const float SCL = 0.08838834764831845f * 1.44269504088896f;

    const uint32_t a_row = lane & 15, a_chk = lane >> 4;
    const uint32_t b_row = ((lane >> 4) & 1) * 8 + (lane & 7);
    const uint32_t b_chk = (lane >> 3) & 1;

    for (int kt = 0; kt <= qt; kt++) {
        MBAR_WAIT(sbb + 8, kt & 1);
        if (kt == 0) MBAR_WAIT(sbb, 0);

        #pragma unroll
        for (int nt = 0; nt < 16; nt++)
            #pragma unroll
            for (int j = 0; j < 4; j++) sc[nt][j] = 0.f;

        #pragma unroll
        for (int kc = 0; kc < 8; kc++) {
            const uint32_t db = (kc >> 2) * 16384u;
            const uint32_t acol = ((uint32_t)(kc * 16) + a_chk * 8u) & 63u;
            uint32_t a[4];
            ldsm_x4(a, QS + db + SWZ((uint32_t)(wq + a_row) * 128u + acol * 2u));
            const uint32_t bcol = ((uint32_t)(kc * 16) + b_chk * 8u) & 63u;
            #pragma unroll
            for (int p = 0; p < 8; p++) {
                uint32_t rr[4];
                ldsm_x4(rr, KS + db + SWZ((uint32_t)(p * 16 + b_row) * 128u + bcol * 2u));
                uint32_t b0[2] = {rr[0], rr[1]}, b1[2] = {rr[2], rr[3]};
                mma_fp16(sc[2*p],   a, b0);
                mma_fp16(sc[2*p+1], a, b1);
            }
        }
        __syncthreads();
        if (tid == 0 && kt < qt) {
            const int nt1 = kt + 1;
            MBAR_EXPECT(sbb + 8, 49152u);
            bulk_g2s(KS, (const char*)Kg + ((size_t)(h * 16 + nt1) << 15), 32768u, sbb + 8);
            bulk_g2s(VS + ((uint32_t)(nt1 & 1)) * 16384u,
                     (const char*)Vg + ((size_t)(h * 16 + nt1) << 14), 16384u, sbb + 8);
        }

        const bool diag = (kt == qt);
        float nm0 = m0, nm1 = m1;
        #pragma unroll
        for (int nt = 0; nt < 16; nt++) {
            #pragma unroll
            for (int j = 0; j < 4; j++) {
                float v = sc[nt][j] * SCL;
                if (diag) {
                    int col = nt * 8 + c2 + (j & 1);
                    int rowl = wq + r + (j >> 1) * 8;
                    if (col > rowl) v = -1e30f;
                }
                sc[nt][j] = v;
            }
            nm0 = fmaxf(nm0, fmaxf(sc[nt][0], sc[nt][1]));
            nm1 = fmaxf(nm1, fmaxf(sc[nt][2], sc[nt][3]));
        }
        #pragma unroll
        for (int off = 1; off <= 2; off <<= 1) {
            nm0 = fmaxf(nm0, __shfl_xor_sync(0xffffffffu, nm0, off));
            nm1 = fmaxf(nm1, __shfl_xor_sync(0xffffffffu, nm1, off));
        }
        float rs0 = 0.f, rs1 = 0.f;
        #pragma unroll
        for (int nt = 0; nt < 16; nt++) {
            sc[nt][0] = exp2f(sc[nt][0] - nm0);
            sc[nt][1] = exp2f(sc[nt][1] - nm0);
            sc[nt][2] = exp2f(sc[nt][2] - nm1);
            sc[nt][3] = exp2f(sc[nt][3] - nm1);
            rs0 += sc[nt][0] + sc[nt][1];
            rs1 += sc[nt][2] + sc[nt][3];
        }
        #pragma unroll
        for (int off = 1; off <= 2; off <<= 1) {
            rs0 += __shfl_xor_sync(0xffffffffu, rs0, off);
            rs1 += __shfl_xor_sync(0xffffffffu, rs1, off);
        }
        float cr0 = exp2f(m0 - nm0), cr1 = exp2f(m1 - nm1);
        l0 = l0 * cr0 + rs0; l1 = l1 * cr1 + rs1;
        m0 = nm0; m1 = nm1;
        #pragma unroll
        for (int i = 0; i < 8; i++) {
            o[i][0] *= cr0; o[i][1] *= cr0;
            o[i][2] *= cr1; o[i][3] *= cr1;
        }

        const uint32_t vbase = VS + ((uint32_t)(kt & 1)) * 16384u;
        #pragma unroll
        for (int kc = 0; kc < 8; kc++) {
            uint32_t a[4];
            a[0] = pack2(sc[2*kc][0],   sc[2*kc][1]);
            a[1] = pack2(sc[2*kc][2],   sc[2*kc][3]);
            a[2] = pack2(sc[2*kc+1][0], sc[2*kc+1][1]);
            a[3] = pack2(sc[2*kc+1][2], sc[2*kc+1][3]);
            const uint32_t scol = (uint32_t)(kc * 16) + b_chk * 8u;
            const uint32_t sub = (scol >> 6) * 8192u;
            #pragma unroll
            for (int p = 0; p < 4; p++) {
                uint32_t rr[4];
                ldsm_x4(rr, vbase + sub + SWZ((uint32_t)(p * 16 + b_row) * 128u + (scol & 63u) * 2u));
                uint32_t b0[2] = {rr[0], rr[1]}, b1[2] = {rr[2], rr[3]};
                mma_fp16(o[2*p],   a, b0);
                mma_fp16(o[2*p+1], a, b1);
            }
        }
    }

    const float i0 = 1.f / l0, i1 = 1.f / l1;
    #pragma unroll
    for (int nt = 0; nt < 8; nt++) {
        const int col = h * DV + nt * 8 + c2;
        #pragma unroll
        for (int half = 0; half < 2; half++) {
            const int row = qt * 128 + wq + r + half * 8;
            float inv = half ? i1 : i0;
            float v0 = o[nt][half * 2 + 0] * inv;
            float v1 = o[nt][half * 2 + 1] * inv;
            uint32_t inner = (uint32_t)(row & 127) * 128u + (uint32_t)(col & 63) * 2u;
            size_t off = (((size_t)(row >> 7) * KB_CTX + (col >> 6)) << 14) + SWZ(inner);
            *(uint32_t*)((char*)Cf + off) = pack2(v0, v1);
        }
    }
}

// ---------------------------------------------------------------- launch
extern "C" void kernel_launch(void* const* d_in, const int* in_sizes, int n_in,
                              void* d_out, int out_size)
{
    const int*   positions = (const int*)  d_in[0];
    const float* hidden    = (const float*)d_in[1];
    const float* in_ln     = (const float*)d_in[2];
    const float* qw        = (const float*)d_in[3];
    const float* kva_w     = (const float*)d_in[4];
    const float* kvaln     = (const float*)d_in[5];
    const float* kvb_w     = (const float*)d_in[6];
    const float* ow        = (const float*)d_in[7];
    const float* postln    = (const float*)d_in[8];
    const float* gatew     = (const float*)d_in[9];
    const float* fc1w      = (const float*)d_in[10];
    const float* fc2w      = (const float*)d_in[11];
    float* out = (float*)d_out;

    float *sa, *qb, *ckv, *kvn, *kvv, *x2, *mlp, *pr;
    cudaGetSymbolAddress((void**)&sa,  g_sa);
    cudaGetSymbolAddress((void**)&qb,  g_q);
    cudaGetSymbolAddress((void**)&ckv, g_ckv);
    cudaGetSymbolAddress((void**)&kvn, g_kvn);
    cudaGetSymbolAddress((void**)&kvv, g_kv);
    cudaGetSymbolAddress((void**)&x2,  g_x2);
    cudaGetSymbolAddress((void**)&mlp, g_mlp);
    cudaGetSymbolAddress((void**)&pr,  g_pr);

    __half *saf,*kvnf,*mlpf,*ctxf,*hbf,*qwf,*kvaf,*kbwf,*owf,*f1f,*f2f,*qbf,*kbf,*vtf;
    cudaGetSymbolAddress((void**)&saf,  g_sa_f);
    cudaGetSymbolAddress((void**)&kvnf, g_kvn_f);
    cudaGetSymbolAddress((void**)&mlpf, g_mlp_f);
    cudaGetSymbolAddress((void**)&ctxf, g_ctx_f);
    cudaGetSymbolAddress((void**)&hbf,  g_hb_f);
    cudaGetSymbolAddress((void**)&qwf,  g_qw_f);
    cudaGetSymbolAddress((void**)&kvaf, g_kva_f);
    cudaGetSymbolAddress((void**)&kbwf, g_kbw_f);
    cudaGetSymbolAddress((void**)&owf,  g_ow_f);
    cudaGetSymbolAddress((void**)&f1f,  g_f1_f);
    cudaGetSymbolAddress((void**)&f2f,  g_f2_f);
    cudaGetSymbolAddress((void**)&qbf,  g_qb_f);
    cudaGetSymbolAddress((void**)&kbf,  g_kb_f);
    cudaGetSymbolAddress((void**)&vtf,  g_vt_f);

    cudaFuncSetAttribute(bgemm<0>, cudaFuncAttributeMaxDynamicSharedMemorySize, BG_SMEM);
    cudaFuncSetAttribute(bgemm<1>, cudaFuncAttributeMaxDynamicSharedMemorySize, BG_SMEM);
    cudaFuncSetAttribute(bgemm<2>, cudaFuncAttributeMaxDynamicSharedMemorySize, BG_SMEM);
    cudaFuncSetAttribute(attn_tc,  cudaFuncAttributeMaxDynamicSharedMemorySize, AT_SMEM);

    static cudaStream_t s2 = nullptr;
    static cudaEvent_t evFork = nullptr, evQKA = nullptr, evKBW = nullptr,
                       evOW = nullptr, evF1 = nullptr, evF2 = nullptr;
    if (s2 == nullptr) {
        cudaStreamCreateWithFlags(&s2, cudaStreamNonBlocking);
        cudaEventCreateWithFlags(&evFork, cudaEventDisableTiming);
        cudaEventCreateWithFlags(&evQKA,  cudaEventDisableTiming);
        cudaEventCreateWithFlags(&evKBW,  cudaEventDisableTiming);
        cudaEventCreateWithFlags(&evOW,   cudaEventDisableTiming);
        cudaEventCreateWithFlags(&evF1,   cudaEventDisableTiming);
        cudaEventCreateWithFlags(&evF2,   cudaEventDisableTiming);
    }

    // fork: weight converts on s2
    cudaEventRecord(evFork, 0);
    cudaStreamWaitEvent(s2, evFork, 0);
    cvt_blk_kernel<<<2048, 256, 0, s2>>>(qw,    qwf,  H_DIM, H_DIM, H_DIM);
    cvt_blk_kernel<<<512,  256, 0, s2>>>(kva_w, kvaf, CKV_P, KVR + 64, H_DIM);
    cudaEventRecord(evQKA, s2);
    cvt_blk_kernel<<<512,  256, 0, s2>>>(kvb_w, kbwf, H_DIM, H_DIM, KVR);
    cudaEventRecord(evKBW, s2);
    cvt_blk_kernel<<<1024, 256, 0, s2>>>(ow,    owf,  H_DIM, H_DIM, NHEAD * DV);
    cudaEventRecord(evOW, s2);
    cvt_blk_kernel<<<4096, 256, 0, s2>>>(fc1w,  f1f,  NFC1, NFC1, H_DIM);
    cudaEventRecord(evF1, s2);
    cvt_fc2_blk_kernel<<<4096, 256, 0, s2>>>(fc2w, f2f);
    cudaEventRecord(evF2, s2);

    // 1. input RMSNorm
    rmsnorm_kernel<<<S_LEN, 256>>>(hidden, in_ln, sa, saf, H_DIM, H_DIM, KB_H);
    // 2+3. merged q projection (blocks 0..15) + kv_a (blocks 16..19)
    cudaStreamWaitEvent(0, evQKA, 0);
    bgemm<0><<<dim3(20, 16), 256, BG_SMEM>>>(saf, qwf, H_DIM, KB_H,
        qb, nullptr, nullptr, 0, kvaf, ckv, 16, CKV_P);
    // 4. kv RMSNorm
    rmsnorm_kernel<<<S_LEN, 256>>>(ckv, kvaln, kvn, kvnf, KVR, CKV_P, KB_KVR);
    // 5. kv_b projection
    cudaStreamWaitEvent(0, evKBW, 0);
    bgemm<0><<<dim3(16, 16), 256, BG_SMEM>>>(kvnf, kbwf, H_DIM, KB_KVR,
        kvv, nullptr, nullptr, 0, nullptr, nullptr, 0, 0);
    // 6+7. fused rope + attention operand converts
    qk_cvt_kernel<<<S_LEN, 256>>>(positions, qb, kvv, ckv, qbf, kbf);
    vt_cvt_kernel<<<dim3(S_LEN / 128, NHEAD), 256>>>(kvv, vtf);
    // 8. tensor-core attention
    attn_tc<<<256, 256, AT_SMEM>>>(qbf, kbf, vtf, ctxf);
    // 9. o projection + residual
    cudaStreamWaitEvent(0, evOW, 0);
    bgemm<2><<<dim3(16, 16), 256, BG_SMEM>>>(ctxf, owf, H_DIM, KB_CTX,
        x2, hidden, nullptr, 0, nullptr, nullptr, 0, 0);
    // 10. post RMSNorm
    rmsnorm_kernel<<<S_LEN, 256>>>(x2, postln, mlp, mlpf, H_DIM, H_DIM, KB_H);
    // 11. gate softmax
    gate_kernel<<<S_LEN, 256>>>(mlp, gatew, pr);
    // 12. fc1 + SiLU*probs
    cudaStreamWaitEvent(0, evF1, 0);
    bgemm<1><<<dim3(NFC1 / 128, 16), 256, BG_SMEM>>>(mlpf, f1f, NFC1, KB_H,
        nullptr, pr, hbf, KB_FC2, nullptr, nullptr, 0, 0);
    // 13. fc2 + residual -> out
    cudaStreamWaitEvent(0, evF2, 0);
    bgemm<2><<<dim3(16, 16), 256, BG_SMEM>>>(hbf, f2f, H_DIM, KB_FC2,
        out, x2, nullptr, 0, nullptr, nullptr, 0, 0);
}